// round 1
// baseline (speedup 1.0000x reference)
#include <cuda_runtime.h>
#include <cuda_bf16.h>
#include <math.h>

// ---------------- problem constants ----------------
#define B    64
#define NF   196
#define ENC  2048
#define DEC  512
#define ATT  512
#define VOC  30000
#define EMB  512
#define TSTEPS 24          // captions.shape[1]-1 = 25-1
#define KCAT (EMB + ENC + DEC)   // 3072
#define GATES4 (4*DEC)           // 2048

#define ALPHA_OFF ((size_t)B * TSTEPS * VOC)   // 46,080,000

// ---------------- scratch (device global; no allocation allowed) ----------------
// offsets in floats
#define OFF_UHS    ((size_t)0)                         // B*NF*ATT = 6,422,528
#define OFF_WCAT   (OFF_UHS + (size_t)B*NF*ATT)        // KCAT*GATES4 = 6,291,456
#define OFF_MEANF  (OFF_WCAT + (size_t)KCAT*GATES4)    // B*ENC
#define OFF_H      (OFF_MEANF + (size_t)B*ENC)
#define OFF_C      (OFF_H + (size_t)B*DEC)
#define OFF_WAH    (OFF_C + (size_t)B*DEC)
#define OFF_CTX    (OFF_WAH + (size_t)B*ATT)
#define OFF_INCAT  (OFF_CTX + (size_t)B*ENC)
#define OFF_GATES  (OFF_INCAT + (size_t)B*KCAT)
#define OFF_BCAT   (OFF_GATES + (size_t)B*GATES4)
#define SCRATCH_TOTAL (OFF_BCAT + (size_t)GATES4)

__device__ float g_scratch[SCRATCH_TOTAL];

// ---------------- helpers ----------------
__device__ __forceinline__ float sigmoidf_(float x) {
    return 1.0f / (1.0f + expf(-x));
}

// ---------------- prep: Wcat = [W_ih ; W_hh], bcat = b_ih + b_hh ----------------
__global__ void prep_wcat_kernel(const float* __restrict__ W_ih,
                                 const float* __restrict__ W_hh,
                                 const float* __restrict__ b_ih,
                                 const float* __restrict__ b_hh,
                                 float* __restrict__ Wcat,
                                 float* __restrict__ bcat) {
    int total = KCAT * GATES4;
    for (int i = blockIdx.x * blockDim.x + threadIdx.x; i < total;
         i += gridDim.x * blockDim.x) {
        int r = i / GATES4;
        int c = i - r * GATES4;
        Wcat[i] = (r < EMB + ENC) ? W_ih[i] : W_hh[(r - (EMB + ENC)) * GATES4 + c];
    }
    int idx = blockIdx.x * blockDim.x + threadIdx.x;
    if (idx < GATES4) bcat[idx] = b_ih[idx] + b_hh[idx];
}

// ---------------- mean over NF ----------------
__global__ void meanf_kernel(const float* __restrict__ features,
                             float* __restrict__ meanf) {
    int idx = blockIdx.x * blockDim.x + threadIdx.x;
    if (idx < B * ENC) {
        int b = idx >> 11;         // /2048
        int e = idx & (ENC - 1);
        const float* p = features + (size_t)b * NF * ENC + e;
        float s = 0.f;
        #pragma unroll 4
        for (int f = 0; f < NF; ++f) s += p[(size_t)f * ENC];
        meanf[idx] = s * (1.0f / (float)NF);
    }
}

// ---------------- init C rows with bias ----------------
__global__ void init_rows_kernel(float* __restrict__ C,
                                 const float* __restrict__ bias,
                                 int total, int cols) {
    int i = blockIdx.x * blockDim.x + threadIdx.x;
    if (i < total) C[i] = bias[i % cols];
}

// ---------------- generic tiled SGEMM: C(M,N) = A(M,K) @ B(K,N) ----------------
// block tile 64x64, 256 threads, 4x4 per thread, K-chunk 32.
// ATOMIC=true: atomicAdd into pre-initialized C (used with K-split via gridDim.z)
// ATOMIC=false: C = acc + bias  (gridDim.z must be 1)
// Requirements: M % 64 == 0, K % (32*gridDim.z) == 0. N may be arbitrary.
template <bool ATOMIC>
__global__ void __launch_bounds__(256)
sgemm_kernel(const float* __restrict__ A, int lda,
             const float* __restrict__ Bm, int ldb,
             float* __restrict__ C, int ldc,
             const float* __restrict__ bias,
             int M, int N, int K) {
    __shared__ float As[64][33];   // [m][k], padded
    __shared__ float Bs[32][64];   // [k][n]

    const int m0 = blockIdx.y * 64;
    const int n0 = blockIdx.x * 64;
    const int chunks_total = K / 32;
    const int chunks_per = chunks_total / gridDim.z;
    const int kc0 = blockIdx.z * chunks_per;

    const int tid = threadIdx.x;
    const int tx = tid & 15;       // 0..15 col group
    const int ty = tid >> 4;       // 0..15 row group

    float acc[4][4];
    #pragma unroll
    for (int i = 0; i < 4; i++)
        #pragma unroll
        for (int j = 0; j < 4; j++) acc[i][j] = 0.f;

    for (int cc = 0; cc < chunks_per; ++cc) {
        const int k0 = (kc0 + cc) * 32;
        // load A chunk: 64x32, k fastest across tid for coalescing
        #pragma unroll
        for (int i = 0; i < 8; ++i) {
            int e = tid + i * 256;
            int k = e & 31;
            int m = e >> 5;
            As[m][k] = A[(size_t)(m0 + m) * lda + k0 + k];
        }
        // load B chunk: 32x64, n fastest
        #pragma unroll
        for (int i = 0; i < 8; ++i) {
            int e = tid + i * 256;
            int n = e & 63;
            int k = e >> 6;
            int col = n0 + n;
            Bs[k][n] = (col < N) ? Bm[(size_t)(k0 + k) * ldb + col] : 0.f;
        }
        __syncthreads();
        #pragma unroll
        for (int k = 0; k < 32; ++k) {
            float a0 = As[ty * 4 + 0][k];
            float a1 = As[ty * 4 + 1][k];
            float a2 = As[ty * 4 + 2][k];
            float a3 = As[ty * 4 + 3][k];
            float4 bv = *reinterpret_cast<const float4*>(&Bs[k][tx * 4]);
            acc[0][0] += a0 * bv.x; acc[0][1] += a0 * bv.y; acc[0][2] += a0 * bv.z; acc[0][3] += a0 * bv.w;
            acc[1][0] += a1 * bv.x; acc[1][1] += a1 * bv.y; acc[1][2] += a1 * bv.z; acc[1][3] += a1 * bv.w;
            acc[2][0] += a2 * bv.x; acc[2][1] += a2 * bv.y; acc[2][2] += a2 * bv.z; acc[2][3] += a2 * bv.w;
            acc[3][0] += a3 * bv.x; acc[3][1] += a3 * bv.y; acc[3][2] += a3 * bv.z; acc[3][3] += a3 * bv.w;
        }
        __syncthreads();
    }

    #pragma unroll
    for (int i = 0; i < 4; ++i) {
        int row = m0 + ty * 4 + i;
        #pragma unroll
        for (int j = 0; j < 4; ++j) {
            int col = n0 + tx * 4 + j;
            if (col < N) {
                if (ATOMIC) {
                    atomicAdd(&C[(size_t)row * ldc + col], acc[i][j]);
                } else {
                    float bv = bias ? bias[col] : 0.f;
                    C[(size_t)row * ldc + col] = acc[i][j] + bv;
                }
            }
        }
    }
}

// ---------------- fused attention: scores -> softmax -> context ----------------
// one block per batch element b, 256 threads
__global__ void __launch_bounds__(256)
attention_kernel(const float* __restrict__ uhs,
                 const float* __restrict__ wah,
                 const float* __restrict__ Aw,
                 const float* __restrict__ Ab,
                 const float* __restrict__ features,
                 float* __restrict__ ctx,
                 float* __restrict__ alpha_out /* d_out + ALPHA_OFF + t*NF */) {
    const int b = blockIdx.x;
    const int tid = threadIdx.x;
    const int warp = tid >> 5;
    const int lane = tid & 31;

    __shared__ float s_wah[ATT];
    __shared__ float s_Aw[ATT];
    __shared__ float s_sc[NF];
    __shared__ float s_pmax[8];
    __shared__ float s_psum[8];

    for (int i = tid; i < ATT; i += 256) {
        s_wah[i] = wah[b * ATT + i];
        s_Aw[i]  = Aw[i];
    }
    __syncthreads();

    const float Ab0 = Ab[0];
    // scores
    for (int f = warp; f < NF; f += 8) {
        const float* u = uhs + ((size_t)(b * NF + f)) * ATT;
        float acc = 0.f;
        #pragma unroll 4
        for (int k = lane; k < ATT; k += 32)
            acc += tanhf(u[k] + s_wah[k]) * s_Aw[k];
        #pragma unroll
        for (int o = 16; o; o >>= 1) acc += __shfl_xor_sync(0xffffffffu, acc, o);
        if (lane == 0) s_sc[f] = acc + Ab0;
    }
    __syncthreads();

    // softmax over NF=196
    float v = (tid < NF) ? s_sc[tid] : -1e30f;
    float m = v;
    #pragma unroll
    for (int o = 16; o; o >>= 1) m = fmaxf(m, __shfl_xor_sync(0xffffffffu, m, o));
    if (lane == 0) s_pmax[warp] = m;
    __syncthreads();
    if (tid == 0) {
        float mm = s_pmax[0];
        #pragma unroll
        for (int w = 1; w < 8; ++w) mm = fmaxf(mm, s_pmax[w]);
        s_pmax[0] = mm;
    }
    __syncthreads();
    const float mx = s_pmax[0];
    float e = (tid < NF) ? expf(v - mx) : 0.f;
    float s = e;
    #pragma unroll
    for (int o = 16; o; o >>= 1) s += __shfl_xor_sync(0xffffffffu, s, o);
    if (lane == 0) s_psum[warp] = s;
    __syncthreads();
    if (tid == 0) {
        float ss = 0.f;
        #pragma unroll
        for (int w = 0; w < 8; ++w) ss += s_psum[w];
        s_psum[0] = ss;
    }
    __syncthreads();
    const float inv_denom = 1.0f / s_psum[0];
    if (tid < NF) {
        float alpha = e * inv_denom;
        s_sc[tid] = alpha;
        alpha_out[(size_t)b * (TSTEPS * NF) + tid] = alpha;
    }
    __syncthreads();

    // context[b,e] = sum_f alpha[f] * features[b,f,e]
    const float* fbase = features + (size_t)b * NF * ENC;
    for (int e2 = tid; e2 < ENC; e2 += 256) {
        float acc = 0.f;
        const float* fp = fbase + e2;
        #pragma unroll 4
        for (int f = 0; f < NF; ++f) acc += s_sc[f] * fp[(size_t)f * ENC];
        ctx[b * ENC + e2] = acc;
    }
}

// ---------------- build [x_t, context, h] ----------------
__global__ void build_incat_kernel(const int* __restrict__ captions,
                                   const float* __restrict__ emb,
                                   const float* __restrict__ ctx,
                                   const float* __restrict__ h,
                                   float* __restrict__ incat,
                                   int t) {
    int idx = blockIdx.x * blockDim.x + threadIdx.x;
    if (idx >= B * KCAT) return;
    int b = idx / KCAT;
    int c = idx - b * KCAT;
    float v;
    if (c < EMB) {
        int tok = captions[b * (TSTEPS + 1) + t];
        v = emb[(size_t)tok * EMB + c];
    } else if (c < EMB + ENC) {
        v = ctx[b * ENC + (c - EMB)];
    } else {
        v = h[b * DEC + (c - EMB - ENC)];
    }
    incat[idx] = v;
}

// ---------------- LSTM pointwise ----------------
__global__ void lstm_kernel(const float* __restrict__ gates,
                            float* __restrict__ h,
                            float* __restrict__ c) {
    int idx = blockIdx.x * blockDim.x + threadIdx.x;
    if (idx >= B * DEC) return;
    int b = idx / DEC;
    int n = idx - b * DEC;
    const float* g = gates + b * GATES4;
    float i_ = g[n];
    float f_ = g[DEC + n];
    float gg = g[2 * DEC + n];
    float o_ = g[3 * DEC + n];
    float cc = c[idx];
    cc = sigmoidf_(f_) * cc + sigmoidf_(i_) * tanhf(gg);
    c[idx] = cc;
    h[idx] = sigmoidf_(o_) * tanhf(cc);
}

// ---------------- launch ----------------
extern "C" void kernel_launch(void* const* d_in, const int* in_sizes, int n_in,
                              void* d_out, int out_size) {
    const float* features = (const float*)d_in[0];
    const int*   captions = (const int*)  d_in[1];
    const float* emb      = (const float*)d_in[2];
    const float* Uw       = (const float*)d_in[3];
    const float* Ub       = (const float*)d_in[4];
    const float* Ww       = (const float*)d_in[5];
    const float* Wb       = (const float*)d_in[6];
    const float* Aw       = (const float*)d_in[7];
    const float* Ab       = (const float*)d_in[8];
    const float* ih_w     = (const float*)d_in[9];
    const float* ih_b     = (const float*)d_in[10];
    const float* ic_w     = (const float*)d_in[11];
    const float* ic_b     = (const float*)d_in[12];
    const float* W_ih     = (const float*)d_in[13];
    const float* b_ih     = (const float*)d_in[14];
    const float* W_hh     = (const float*)d_in[15];
    const float* b_hh     = (const float*)d_in[16];
    const float* fcn_w    = (const float*)d_in[17];
    const float* fcn_b    = (const float*)d_in[18];
    float* out = (float*)d_out;

    float* S = nullptr;
    cudaGetSymbolAddress((void**)&S, g_scratch);
    float* uhs   = S + OFF_UHS;
    float* Wcat  = S + OFF_WCAT;
    float* meanf = S + OFF_MEANF;
    float* h     = S + OFF_H;
    float* c     = S + OFF_C;
    float* wah   = S + OFF_WAH;
    float* ctx   = S + OFF_CTX;
    float* incat = S + OFF_INCAT;
    float* gates = S + OFF_GATES;
    float* bcat  = S + OFF_BCAT;

    // ---- prep ----
    prep_wcat_kernel<<<2048, 256>>>(W_ih, W_hh, b_ih, b_hh, Wcat, bcat);
    meanf_kernel<<<(B * ENC + 255) / 256, 256>>>(features, meanf);
    init_rows_kernel<<<(B * DEC + 255) / 256, 256>>>(h, ih_b, B * DEC, DEC);
    init_rows_kernel<<<(B * DEC + 255) / 256, 256>>>(c, ic_b, B * DEC, DEC);
    // h0 = meanf @ ih_w (+ih_b already in h); K=2048, split 8
    sgemm_kernel<true><<<dim3(DEC / 64, 1, 8), 256>>>(meanf, ENC, ih_w, DEC, h, DEC,
                                                      nullptr, B, DEC, ENC);
    sgemm_kernel<true><<<dim3(DEC / 64, 1, 8), 256>>>(meanf, ENC, ic_w, DEC, c, DEC,
                                                      nullptr, B, DEC, ENC);
    // u_hs = features @ Uw + Ub  (12544 x 512 x 2048)
    sgemm_kernel<false><<<dim3(ATT / 64, (B * NF) / 64, 1), 256>>>(
        features, ENC, Uw, ATT, uhs, ATT, Ub, B * NF, ATT, ENC);

    // ---- recurrent steps ----
    for (int t = 0; t < TSTEPS; ++t) {
        // w_ah = h @ Ww + Wb   (64 x 512 x 512), K-split 4
        init_rows_kernel<<<(B * ATT + 255) / 256, 256>>>(wah, Wb, B * ATT, ATT);
        sgemm_kernel<true><<<dim3(ATT / 64, 1, 4), 256>>>(h, DEC, Ww, ATT, wah, ATT,
                                                          nullptr, B, ATT, DEC);
        // attention: scores/softmax/context, writes alphas
        attention_kernel<<<B, 256>>>(uhs, wah, Aw, Ab, features, ctx,
                                     out + ALPHA_OFF + (size_t)t * NF);
        // incat = [x_t, ctx, h]
        build_incat_kernel<<<(B * KCAT + 255) / 256, 256>>>(captions, emb, ctx, h,
                                                            incat, t);
        // gates = incat @ Wcat + bcat   (64 x 2048 x 3072), K-split 6
        init_rows_kernel<<<(B * GATES4 + 255) / 256, 256>>>(gates, bcat, B * GATES4,
                                                            GATES4);
        sgemm_kernel<true><<<dim3(GATES4 / 64, 1, 6), 256>>>(incat, KCAT, Wcat, GATES4,
                                                             gates, GATES4, nullptr,
                                                             B, GATES4, KCAT);
        // LSTM pointwise -> h, c
        lstm_kernel<<<(B * DEC + 255) / 256, 256>>>(gates, h, c);
        // preds_t = h @ fcn_w + fcn_b   (64 x 30000 x 512)
        sgemm_kernel<false><<<dim3((VOC + 63) / 64, 1, 1), 256>>>(
            h, DEC, fcn_w, VOC, out + (size_t)t * VOC, TSTEPS * VOC, fcn_b,
            B, VOC, DEC);
    }
}

// round 2
// speedup vs baseline: 1.2498x; 1.2498x over previous
#include <cuda_runtime.h>
#include <math.h>
#include <stdint.h>

// ---------------- problem constants ----------------
#define B    64
#define NF   196
#define ENC  2048
#define DEC  512
#define ATT  512
#define VOC  30000
#define EMB  512
#define TSTEPS 24
#define KCAT (EMB + ENC + DEC)   // 3072
#define GATES4 (4*DEC)           // 2048

#define ALPHA_OFF ((size_t)B * TSTEPS * VOC)

// ---------------- scratch ----------------
#define OFF_UHS    ((size_t)0)
#define OFF_WCAT   (OFF_UHS + (size_t)B*NF*ATT)
#define OFF_MEANF  (OFF_WCAT + (size_t)KCAT*GATES4)
#define OFF_H      (OFF_MEANF + (size_t)B*ENC)
#define OFF_C      (OFF_H + (size_t)B*DEC)
#define OFF_WAH    (OFF_C + (size_t)B*DEC)
#define OFF_CTX    (OFF_WAH + (size_t)B*ATT)
#define OFF_INCAT  (OFF_CTX + (size_t)B*ENC)
#define OFF_GATES  (OFF_INCAT + (size_t)B*KCAT)
#define OFF_BCAT   (OFF_GATES + (size_t)B*GATES4)
#define SCRATCH_TOTAL (OFF_BCAT + (size_t)GATES4)

__device__ __align__(16) float g_scratch[SCRATCH_TOTAL];

__device__ __forceinline__ float sigmoidf_(float x) {
    return 1.0f / (1.0f + expf(-x));
}
__device__ __forceinline__ uint32_t f2tf(float x) {
    uint32_t r;
    asm("cvt.rna.tf32.f32 %0, %1;" : "=r"(r) : "f"(x));
    return r;
}

// ---------------- prep: Wcat = [W_ih ; W_hh], bcat = b_ih + b_hh ----------------
__global__ void prep_wcat_kernel(const float* __restrict__ W_ih,
                                 const float* __restrict__ W_hh,
                                 const float* __restrict__ b_ih,
                                 const float* __restrict__ b_hh,
                                 float* __restrict__ Wcat,
                                 float* __restrict__ bcat) {
    int total = KCAT * GATES4;
    for (int i = blockIdx.x * blockDim.x + threadIdx.x; i < total;
         i += gridDim.x * blockDim.x) {
        int r = i / GATES4;
        int c = i - r * GATES4;
        Wcat[i] = (r < EMB + ENC) ? W_ih[i] : W_hh[(r - (EMB + ENC)) * GATES4 + c];
    }
    int idx = blockIdx.x * blockDim.x + threadIdx.x;
    if (idx < GATES4) bcat[idx] = b_ih[idx] + b_hh[idx];
}

// ---------------- mean over NF ----------------
__global__ void meanf_kernel(const float* __restrict__ features,
                             float* __restrict__ meanf) {
    int idx = blockIdx.x * blockDim.x + threadIdx.x;
    if (idx < B * ENC) {
        int b = idx >> 11;
        int e = idx & (ENC - 1);
        const float* p = features + (size_t)b * NF * ENC + e;
        float s = 0.f;
        #pragma unroll 4
        for (int f = 0; f < NF; ++f) s += p[(size_t)f * ENC];
        meanf[idx] = s * (1.0f / (float)NF);
    }
}

// ---------------- init rows with bias ----------------
__global__ void init_rows_kernel(float* __restrict__ C,
                                 const float* __restrict__ bias,
                                 int total, int cols) {
    int i = blockIdx.x * blockDim.x + threadIdx.x;
    if (i < total) C[i] = bias[i % cols];
}

// ---------------- tf32 tensor-core GEMM: C(M,N) = A(M,K) @ B(K,N) ----------------
// block tile 64x128, 8 warps (2 M x 4 N), warp tile 32x32 via mma.m16n8k8.
// Requirements: m0+64 <= M, K % (32*gridDim.z) == 0, N % 4 == 0 (for float4 B loads).
// ATOMIC=true: atomicAdd into pre-initialized C. ATOMIC=false: C = acc + bias.
template <bool ATOMIC>
__global__ void __launch_bounds__(256)
tf32_gemm(const float* __restrict__ A, int lda,
          const float* __restrict__ Bm, int ldb,
          float* __restrict__ C, int ldc,
          const float* __restrict__ bias,
          int M, int N, int K) {
    __shared__ uint32_t As[64][36];    // [m][k], stride 36 (bank-conflict-free frags)
    __shared__ uint32_t Bs[32][136];   // [k][n], stride 136

    const int tid  = threadIdx.x;
    const int lane = tid & 31;
    const int warp = tid >> 5;
    const int wm = warp >> 2;          // 0..1 -> M offset wm*32
    const int wn = warp & 3;           // 0..3 -> N offset wn*32
    const int g = lane >> 2;           // 0..7
    const int t = lane & 3;            // 0..3

    const int m0 = blockIdx.y * 64;
    const int n0 = blockIdx.x * 128;
    const int chunks = (K / 32) / gridDim.z;
    const int kc0 = blockIdx.z * chunks;

    float acc[2][4][4];
    #pragma unroll
    for (int mi = 0; mi < 2; ++mi)
        #pragma unroll
        for (int ni = 0; ni < 4; ++ni)
            #pragma unroll
            for (int q = 0; q < 4; ++q) acc[mi][ni][q] = 0.f;

    const int arow = tid >> 3;           // 0..31
    const int ac4  = (tid & 7) * 4;      // 0,4,...,28

    for (int cc = 0; cc < chunks; ++cc) {
        const int k0 = (kc0 + cc) * 32;
        // load A tile 64x32 (2 float4 per thread)
        #pragma unroll
        for (int i = 0; i < 2; ++i) {
            int r = arow + i * 32;
            float4 v = *reinterpret_cast<const float4*>(
                A + (size_t)(m0 + r) * lda + k0 + ac4);
            uint4 u = make_uint4(f2tf(v.x), f2tf(v.y), f2tf(v.z), f2tf(v.w));
            *reinterpret_cast<uint4*>(&As[r][ac4]) = u;
        }
        // load B tile 32x128 (4 float4 per thread)
        #pragma unroll
        for (int i = 0; i < 4; ++i) {
            int j = tid + i * 256;
            int r = j >> 5;
            int c = (j & 31) * 4;
            int col = n0 + c;
            float4 v = make_float4(0.f, 0.f, 0.f, 0.f);
            if (col < N)
                v = *reinterpret_cast<const float4*>(
                    Bm + (size_t)(k0 + r) * ldb + col);
            uint4 u = make_uint4(f2tf(v.x), f2tf(v.y), f2tf(v.z), f2tf(v.w));
            *reinterpret_cast<uint4*>(&Bs[r][c]) = u;
        }
        __syncthreads();

        #pragma unroll
        for (int ks = 0; ks < 4; ++ks) {
            const int k8 = ks * 8;
            uint32_t af[2][4];
            #pragma unroll
            for (int mi = 0; mi < 2; ++mi) {
                int r = wm * 32 + mi * 16 + g;
                af[mi][0] = As[r][k8 + t];
                af[mi][1] = As[r + 8][k8 + t];
                af[mi][2] = As[r][k8 + t + 4];
                af[mi][3] = As[r + 8][k8 + t + 4];
            }
            #pragma unroll
            for (int ni = 0; ni < 4; ++ni) {
                int cB = wn * 32 + ni * 8 + g;
                uint32_t b0 = Bs[k8 + t][cB];
                uint32_t b1 = Bs[k8 + t + 4][cB];
                #pragma unroll
                for (int mi = 0; mi < 2; ++mi) {
                    asm volatile(
                        "mma.sync.aligned.m16n8k8.row.col.f32.tf32.tf32.f32 "
                        "{%0,%1,%2,%3}, {%4,%5,%6,%7}, {%8,%9}, {%0,%1,%2,%3};"
                        : "+f"(acc[mi][ni][0]), "+f"(acc[mi][ni][1]),
                          "+f"(acc[mi][ni][2]), "+f"(acc[mi][ni][3])
                        : "r"(af[mi][0]), "r"(af[mi][1]),
                          "r"(af[mi][2]), "r"(af[mi][3]),
                          "r"(b0), "r"(b1));
                }
            }
        }
        __syncthreads();
    }

    // epilogue: c0:(g,2t) c1:(g,2t+1) c2:(g+8,2t) c3:(g+8,2t+1)
    #pragma unroll
    for (int mi = 0; mi < 2; ++mi) {
        int r0 = m0 + wm * 32 + mi * 16 + g;
        #pragma unroll
        for (int ni = 0; ni < 4; ++ni) {
            int col = n0 + wn * 32 + ni * 8 + 2 * t;
            if (col < N) {
                if (ATOMIC) {
                    atomicAdd(&C[(size_t)r0 * ldc + col],           acc[mi][ni][0]);
                    atomicAdd(&C[(size_t)r0 * ldc + col + 1],       acc[mi][ni][1]);
                    atomicAdd(&C[(size_t)(r0 + 8) * ldc + col],     acc[mi][ni][2]);
                    atomicAdd(&C[(size_t)(r0 + 8) * ldc + col + 1], acc[mi][ni][3]);
                } else {
                    float bv0 = bias ? bias[col] : 0.f;
                    float bv1 = bias ? bias[col + 1] : 0.f;
                    float2 v0 = make_float2(acc[mi][ni][0] + bv0, acc[mi][ni][1] + bv1);
                    float2 v1 = make_float2(acc[mi][ni][2] + bv0, acc[mi][ni][3] + bv1);
                    *reinterpret_cast<float2*>(&C[(size_t)r0 * ldc + col]) = v0;
                    *reinterpret_cast<float2*>(&C[(size_t)(r0 + 8) * ldc + col]) = v1;
                }
            }
        }
    }
}

// ---------------- fused attention (fp32 for accuracy) ----------------
__global__ void __launch_bounds__(256)
attention_kernel(const float* __restrict__ uhs,
                 const float* __restrict__ wah,
                 const float* __restrict__ Aw,
                 const float* __restrict__ Ab,
                 const float* __restrict__ features,
                 float* __restrict__ ctx,
                 float* __restrict__ alpha_out) {
    const int b = blockIdx.x;
    const int tid = threadIdx.x;
    const int warp = tid >> 5;
    const int lane = tid & 31;

    __shared__ float s_wah[ATT];
    __shared__ float s_Aw[ATT];
    __shared__ float s_sc[NF];
    __shared__ float s_pmax[8];
    __shared__ float s_psum[8];

    for (int i = tid; i < ATT; i += 256) {
        s_wah[i] = wah[b * ATT + i];
        s_Aw[i]  = Aw[i];
    }
    __syncthreads();

    const float Ab0 = Ab[0];
    for (int f = warp; f < NF; f += 8) {
        const float* u = uhs + ((size_t)(b * NF + f)) * ATT;
        float acc = 0.f;
        #pragma unroll 4
        for (int k = lane; k < ATT; k += 32)
            acc += tanhf(u[k] + s_wah[k]) * s_Aw[k];
        #pragma unroll
        for (int o = 16; o; o >>= 1) acc += __shfl_xor_sync(0xffffffffu, acc, o);
        if (lane == 0) s_sc[f] = acc + Ab0;
    }
    __syncthreads();

    float v = (tid < NF) ? s_sc[tid] : -1e30f;
    float m = v;
    #pragma unroll
    for (int o = 16; o; o >>= 1) m = fmaxf(m, __shfl_xor_sync(0xffffffffu, m, o));
    if (lane == 0) s_pmax[warp] = m;
    __syncthreads();
    if (tid == 0) {
        float mm = s_pmax[0];
        #pragma unroll
        for (int w = 1; w < 8; ++w) mm = fmaxf(mm, s_pmax[w]);
        s_pmax[0] = mm;
    }
    __syncthreads();
    const float mx = s_pmax[0];
    float e = (tid < NF) ? expf(v - mx) : 0.f;
    float s = e;
    #pragma unroll
    for (int o = 16; o; o >>= 1) s += __shfl_xor_sync(0xffffffffu, s, o);
    if (lane == 0) s_psum[warp] = s;
    __syncthreads();
    if (tid == 0) {
        float ss = 0.f;
        #pragma unroll
        for (int w = 0; w < 8; ++w) ss += s_psum[w];
        s_psum[0] = ss;
    }
    __syncthreads();
    const float inv_denom = 1.0f / s_psum[0];
    if (tid < NF) {
        float alpha = e * inv_denom;
        s_sc[tid] = alpha;
        alpha_out[(size_t)b * (TSTEPS * NF) + tid] = alpha;
    }
    __syncthreads();

    const float* fbase = features + (size_t)b * NF * ENC;
    for (int e2 = tid; e2 < ENC; e2 += 256) {
        float acc = 0.f;
        const float* fp = fbase + e2;
        #pragma unroll 4
        for (int f = 0; f < NF; ++f) acc += s_sc[f] * fp[(size_t)f * ENC];
        ctx[b * ENC + e2] = acc;
    }
}

// ---------------- build [x_t, context, h] + init gates with bcat ----------------
__global__ void build_incat_kernel(const int* __restrict__ captions,
                                   const float* __restrict__ emb,
                                   const float* __restrict__ ctx,
                                   const float* __restrict__ h,
                                   float* __restrict__ incat,
                                   float* __restrict__ gates,
                                   const float* __restrict__ bcat,
                                   int t) {
    int idx = blockIdx.x * blockDim.x + threadIdx.x;
    if (idx < B * GATES4) gates[idx] = bcat[idx & (GATES4 - 1)];
    if (idx >= B * KCAT) return;
    int b = idx / KCAT;
    int c = idx - b * KCAT;
    float v;
    if (c < EMB) {
        int tok = captions[b * (TSTEPS + 1) + t];
        v = emb[(size_t)tok * EMB + c];
    } else if (c < EMB + ENC) {
        v = ctx[b * ENC + (c - EMB)];
    } else {
        v = h[b * DEC + (c - EMB - ENC)];
    }
    incat[idx] = v;
}

// ---------------- LSTM pointwise + init wah for next step ----------------
__global__ void lstm_kernel(const float* __restrict__ gates,
                            float* __restrict__ h,
                            float* __restrict__ c,
                            float* __restrict__ wah,
                            const float* __restrict__ Wb) {
    int idx = blockIdx.x * blockDim.x + threadIdx.x;
    if (idx >= B * DEC) return;
    int b = idx / DEC;
    int n = idx - b * DEC;
    const float* g = gates + b * GATES4;
    float i_ = g[n];
    float f_ = g[DEC + n];
    float gg = g[2 * DEC + n];
    float o_ = g[3 * DEC + n];
    float cc = c[idx];
    cc = sigmoidf_(f_) * cc + sigmoidf_(i_) * tanhf(gg);
    c[idx] = cc;
    h[idx] = sigmoidf_(o_) * tanhf(cc);
    wah[idx] = Wb[idx & (ATT - 1)];   // bias-init for next wah GEMM
}

// ---------------- launch ----------------
extern "C" void kernel_launch(void* const* d_in, const int* in_sizes, int n_in,
                              void* d_out, int out_size) {
    const float* features = (const float*)d_in[0];
    const int*   captions = (const int*)  d_in[1];
    const float* emb      = (const float*)d_in[2];
    const float* Uw       = (const float*)d_in[3];
    const float* Ub       = (const float*)d_in[4];
    const float* Ww       = (const float*)d_in[5];
    const float* Wb       = (const float*)d_in[6];
    const float* Aw       = (const float*)d_in[7];
    const float* Ab       = (const float*)d_in[8];
    const float* ih_w     = (const float*)d_in[9];
    const float* ih_b     = (const float*)d_in[10];
    const float* ic_w     = (const float*)d_in[11];
    const float* ic_b     = (const float*)d_in[12];
    const float* W_ih     = (const float*)d_in[13];
    const float* b_ih     = (const float*)d_in[14];
    const float* W_hh     = (const float*)d_in[15];
    const float* b_hh     = (const float*)d_in[16];
    const float* fcn_w    = (const float*)d_in[17];
    const float* fcn_b    = (const float*)d_in[18];
    float* out = (float*)d_out;

    float* S = nullptr;
    cudaGetSymbolAddress((void**)&S, g_scratch);
    float* uhs   = S + OFF_UHS;
    float* Wcat  = S + OFF_WCAT;
    float* meanf = S + OFF_MEANF;
    float* h     = S + OFF_H;
    float* c     = S + OFF_C;
    float* wah   = S + OFF_WAH;
    float* ctx   = S + OFF_CTX;
    float* incat = S + OFF_INCAT;
    float* gates = S + OFF_GATES;
    float* bcat  = S + OFF_BCAT;

    // ---- prep ----
    prep_wcat_kernel<<<2048, 256>>>(W_ih, W_hh, b_ih, b_hh, Wcat, bcat);
    meanf_kernel<<<(B * ENC + 255) / 256, 256>>>(features, meanf);
    init_rows_kernel<<<(B * DEC + 255) / 256, 256>>>(h, ih_b, B * DEC, DEC);
    init_rows_kernel<<<(B * DEC + 255) / 256, 256>>>(c, ic_b, B * DEC, DEC);
    // h0 = meanf @ ih_w ; c0 = meanf @ ic_w  (64 x 512 x 2048), K-split 8
    tf32_gemm<true><<<dim3(DEC / 128, 1, 8), 256>>>(meanf, ENC, ih_w, DEC, h, DEC,
                                                    nullptr, B, DEC, ENC);
    tf32_gemm<true><<<dim3(DEC / 128, 1, 8), 256>>>(meanf, ENC, ic_w, DEC, c, DEC,
                                                    nullptr, B, DEC, ENC);
    // wah0 = h0 @ Ww + Wb
    init_rows_kernel<<<(B * ATT + 255) / 256, 256>>>(wah, Wb, B * ATT, ATT);
    tf32_gemm<true><<<dim3(ATT / 128, 1, 4), 256>>>(h, DEC, Ww, ATT, wah, ATT,
                                                    nullptr, B, ATT, DEC);
    // u_hs = features @ Uw + Ub  (12544 x 512 x 2048)
    tf32_gemm<false><<<dim3(ATT / 128, (B * NF) / 64, 1), 256>>>(
        features, ENC, Uw, ATT, uhs, ATT, Ub, B * NF, ATT, ENC);

    // ---- recurrent steps ----
    for (int t = 0; t < TSTEPS; ++t) {
        attention_kernel<<<B, 256>>>(uhs, wah, Aw, Ab, features, ctx,
                                     out + ALPHA_OFF + (size_t)t * NF);
        build_incat_kernel<<<(B * KCAT + 255) / 256, 256>>>(captions, emb, ctx, h,
                                                            incat, gates, bcat, t);
        // gates += incat @ Wcat  (64 x 2048 x 3072), K-split 8
        tf32_gemm<true><<<dim3(GATES4 / 128, 1, 8), 256>>>(incat, KCAT, Wcat, GATES4,
                                                           gates, GATES4, nullptr,
                                                           B, GATES4, KCAT);
        // LSTM pointwise -> h, c; also re-init wah with Wb
        lstm_kernel<<<(B * DEC + 255) / 256, 256>>>(gates, h, c, wah, Wb);
        // wah = h @ Ww + Wb (for next step; computed unconditionally)
        tf32_gemm<true><<<dim3(ATT / 128, 1, 4), 256>>>(h, DEC, Ww, ATT, wah, ATT,
                                                        nullptr, B, ATT, DEC);
        // preds_t = h @ fcn_w + fcn_b  (64 x 30000 x 512)
        tf32_gemm<false><<<dim3((VOC + 127) / 128, 1, 1), 256>>>(
            h, DEC, fcn_w, VOC, out + (size_t)t * VOC, TSTEPS * VOC, fcn_b,
            B, VOC, DEC);
    }
}

// round 3
// speedup vs baseline: 2.2564x; 1.8054x over previous
#include <cuda_runtime.h>
#include <math.h>
#include <stdint.h>

// ---------------- problem constants ----------------
#define B    64
#define NF   196
#define ENC  2048
#define DEC  512
#define ATT  512
#define VOC  30000
#define EMB  512
#define TSTEPS 24
#define KCAT (EMB + ENC + DEC)   // 3072
#define GATES4 (4*DEC)           // 2048

#define ALPHA_OFF ((size_t)B * TSTEPS * VOC)

// ---------------- scratch ----------------
#define OFF_UHS    ((size_t)0)
#define OFF_WCAT   (OFF_UHS + (size_t)B*NF*ATT)
#define OFF_MEANF  (OFF_WCAT + (size_t)KCAT*GATES4)
#define OFF_H      (OFF_MEANF + (size_t)B*ENC)
#define OFF_C      (OFF_H + (size_t)B*DEC)
#define OFF_INCAT  (OFF_C + (size_t)B*DEC)
#define OFF_GATES  (OFF_INCAT + (size_t)B*KCAT)
#define OFF_BCAT   (OFF_GATES + (size_t)B*GATES4)
#define SCRATCH_TOTAL (OFF_BCAT + (size_t)GATES4)

__device__ __align__(16) float g_scratch[SCRATCH_TOTAL];

__device__ __forceinline__ float sigmoidf_(float x) {
    return 1.0f / (1.0f + expf(-x));
}
__device__ __forceinline__ uint32_t f2tf(float x) {
    uint32_t r;
    asm("cvt.rna.tf32.f32 %0, %1;" : "=r"(r) : "f"(x));
    return r;
}

// ---------------- prep: Wcat = [W_ih ; W_hh], bcat = b_ih + b_hh ----------------
__global__ void prep_wcat_kernel(const float* __restrict__ W_ih,
                                 const float* __restrict__ W_hh,
                                 const float* __restrict__ b_ih,
                                 const float* __restrict__ b_hh,
                                 float* __restrict__ Wcat,
                                 float* __restrict__ bcat) {
    int total = KCAT * GATES4;
    for (int i = blockIdx.x * blockDim.x + threadIdx.x; i < total;
         i += gridDim.x * blockDim.x) {
        int r = i / GATES4;
        int c = i - r * GATES4;
        Wcat[i] = (r < EMB + ENC) ? W_ih[i] : W_hh[(r - (EMB + ENC)) * GATES4 + c];
    }
    int idx = blockIdx.x * blockDim.x + threadIdx.x;
    if (idx < GATES4) bcat[idx] = b_ih[idx] + b_hh[idx];
}

// ---------------- mean over NF ----------------
__global__ void meanf_kernel(const float* __restrict__ features,
                             float* __restrict__ meanf) {
    int idx = blockIdx.x * blockDim.x + threadIdx.x;
    if (idx < B * ENC) {
        int b = idx >> 11;
        int e = idx & (ENC - 1);
        const float* p = features + (size_t)b * NF * ENC + e;
        float s0 = 0.f, s1 = 0.f, s2 = 0.f, s3 = 0.f;
        int f = 0;
        #pragma unroll 1
        for (; f + 4 <= NF; f += 4) {
            s0 += p[(size_t)(f + 0) * ENC];
            s1 += p[(size_t)(f + 1) * ENC];
            s2 += p[(size_t)(f + 2) * ENC];
            s3 += p[(size_t)(f + 3) * ENC];
        }
        for (; f < NF; ++f) s0 += p[(size_t)f * ENC];
        meanf[idx] = ((s0 + s1) + (s2 + s3)) * (1.0f / (float)NF);
    }
}

// ---------------- init rows with bias ----------------
__global__ void init_rows_kernel(float* __restrict__ C,
                                 const float* __restrict__ bias,
                                 int total, int cols) {
    int i = blockIdx.x * blockDim.x + threadIdx.x;
    if (i < total) C[i] = bias[i % cols];
}

// ---------------- tf32 tensor-core GEMM, cp.async double-buffered ----------------
// C(M,N) = A(M,K) @ B(K,N). block tile 64x128, 8 warps (2M x 4N), warp 32x32,
// mma.m16n8k8.tf32. B double-buffered via cp.async; A prefetched via registers.
// Requirements: m0+64 <= M, K % (32*gridDim.z) == 0, N % 4 == 0, ldb*4 % 16 == 0.
template <bool ATOMIC>
__global__ void __launch_bounds__(256)
tf32_gemm(const float* __restrict__ A, int lda,
          const float* __restrict__ Bm, int ldb,
          float* __restrict__ C, int ldc,
          const float* __restrict__ bias,
          int M, int N, int K) {
    __shared__ __align__(16) float As[64][36];        // 9.2 KB
    __shared__ __align__(16) float Bs[2][32][136];    // 34.8 KB

    const int tid  = threadIdx.x;
    const int lane = tid & 31;
    const int warp = tid >> 5;
    const int wm = warp >> 2;
    const int wn = warp & 3;
    const int g = lane >> 2;
    const int t = lane & 3;

    const int m0 = blockIdx.y * 64;
    const int n0 = blockIdx.x * 128;
    const int chunks = (K / 32) / gridDim.z;
    const int kc0 = blockIdx.z * chunks;

    const int arow = tid >> 3;           // 0..31
    const int ac4  = (tid & 7) * 4;      // 0..28

    float acc[2][4][4];
    #pragma unroll
    for (int mi = 0; mi < 2; ++mi)
        #pragma unroll
        for (int ni = 0; ni < 4; ++ni)
            #pragma unroll
            for (int q = 0; q < 4; ++q) acc[mi][ni][q] = 0.f;

    float4 areg0, areg1;

    // ---- prologue: A chunk0 -> regs -> smem ; B chunk0 -> cp.async stage0
    {
        const int k0 = kc0 * 32;
        areg0 = *reinterpret_cast<const float4*>(A + (size_t)(m0 + arow) * lda + k0 + ac4);
        areg1 = *reinterpret_cast<const float4*>(A + (size_t)(m0 + arow + 32) * lda + k0 + ac4);
        #pragma unroll
        for (int i = 0; i < 4; ++i) {
            int j = tid + i * 256;
            int r = j >> 5;
            int c4 = (j & 31) * 4;
            int col = n0 + c4;
            const float* src = Bm + (size_t)(k0 + r) * ldb + (col < N ? col : 0);
            uint32_t saddr = (uint32_t)__cvta_generic_to_shared(&Bs[0][r][c4]);
            int sz = (col < N) ? 16 : 0;
            asm volatile("cp.async.cg.shared.global [%0], [%1], 16, %2;\n"
                         :: "r"(saddr), "l"(src), "r"(sz));
        }
        asm volatile("cp.async.commit_group;\n");
        *reinterpret_cast<float4*>(&As[arow][ac4])      = areg0;
        *reinterpret_cast<float4*>(&As[arow + 32][ac4]) = areg1;
    }

    for (int cc = 0; cc < chunks; ++cc) {
        const int st = cc & 1;
        // prefetch chunk cc+1
        if (cc + 1 < chunks) {
            const int k0 = (kc0 + cc + 1) * 32;
            #pragma unroll
            for (int i = 0; i < 4; ++i) {
                int j = tid + i * 256;
                int r = j >> 5;
                int c4 = (j & 31) * 4;
                int col = n0 + c4;
                const float* src = Bm + (size_t)(k0 + r) * ldb + (col < N ? col : 0);
                uint32_t saddr = (uint32_t)__cvta_generic_to_shared(&Bs[st ^ 1][r][c4]);
                int sz = (col < N) ? 16 : 0;
                asm volatile("cp.async.cg.shared.global [%0], [%1], 16, %2;\n"
                             :: "r"(saddr), "l"(src), "r"(sz));
            }
            areg0 = *reinterpret_cast<const float4*>(A + (size_t)(m0 + arow) * lda + k0 + ac4);
            areg1 = *reinterpret_cast<const float4*>(A + (size_t)(m0 + arow + 32) * lda + k0 + ac4);
        }
        asm volatile("cp.async.commit_group;\n");
        asm volatile("cp.async.wait_group 1;\n");
        __syncthreads();

        // compute on As (chunk cc) and Bs[st]
        #pragma unroll
        for (int ks = 0; ks < 4; ++ks) {
            const int k8 = ks * 8;
            uint32_t af[2][4];
            #pragma unroll
            for (int mi = 0; mi < 2; ++mi) {
                int r = wm * 32 + mi * 16 + g;
                af[mi][0] = f2tf(As[r][k8 + t]);
                af[mi][1] = f2tf(As[r + 8][k8 + t]);
                af[mi][2] = f2tf(As[r][k8 + t + 4]);
                af[mi][3] = f2tf(As[r + 8][k8 + t + 4]);
            }
            #pragma unroll
            for (int ni = 0; ni < 4; ++ni) {
                int cB = wn * 32 + ni * 8 + g;
                uint32_t b0 = f2tf(Bs[st][k8 + t][cB]);
                uint32_t b1 = f2tf(Bs[st][k8 + t + 4][cB]);
                #pragma unroll
                for (int mi = 0; mi < 2; ++mi) {
                    asm volatile(
                        "mma.sync.aligned.m16n8k8.row.col.f32.tf32.tf32.f32 "
                        "{%0,%1,%2,%3}, {%4,%5,%6,%7}, {%8,%9}, {%0,%1,%2,%3};"
                        : "+f"(acc[mi][ni][0]), "+f"(acc[mi][ni][1]),
                          "+f"(acc[mi][ni][2]), "+f"(acc[mi][ni][3])
                        : "r"(af[mi][0]), "r"(af[mi][1]),
                          "r"(af[mi][2]), "r"(af[mi][3]),
                          "r"(b0), "r"(b1));
                }
            }
        }
        __syncthreads();
        // stage A chunk cc+1 into smem for next iteration
        if (cc + 1 < chunks) {
            *reinterpret_cast<float4*>(&As[arow][ac4])      = areg0;
            *reinterpret_cast<float4*>(&As[arow + 32][ac4]) = areg1;
        }
    }

    // epilogue: c0:(g,2t) c1:(g,2t+1) c2:(g+8,2t) c3:(g+8,2t+1)
    #pragma unroll
    for (int mi = 0; mi < 2; ++mi) {
        int r0 = m0 + wm * 32 + mi * 16 + g;
        #pragma unroll
        for (int ni = 0; ni < 4; ++ni) {
            int col = n0 + wn * 32 + ni * 8 + 2 * t;
            if (col < N) {
                if (ATOMIC) {
                    atomicAdd(&C[(size_t)r0 * ldc + col],           acc[mi][ni][0]);
                    atomicAdd(&C[(size_t)r0 * ldc + col + 1],       acc[mi][ni][1]);
                    atomicAdd(&C[(size_t)(r0 + 8) * ldc + col],     acc[mi][ni][2]);
                    atomicAdd(&C[(size_t)(r0 + 8) * ldc + col + 1], acc[mi][ni][3]);
                } else {
                    float bv0 = bias ? bias[col] : 0.f;
                    float bv1 = bias ? bias[col + 1] : 0.f;
                    float2 v0 = make_float2(acc[mi][ni][0] + bv0, acc[mi][ni][1] + bv1);
                    float2 v1 = make_float2(acc[mi][ni][2] + bv0, acc[mi][ni][3] + bv1);
                    *reinterpret_cast<float2*>(&C[(size_t)r0 * ldc + col]) = v0;
                    *reinterpret_cast<float2*>(&C[(size_t)(r0 + 8) * ldc + col]) = v1;
                }
            }
        }
    }
}

// ---------------- scores kernel: wah GEMV + scores + softmax + glue ----------------
// one block per batch element b, 256 threads
__global__ void __launch_bounds__(256)
scores_kernel(const float* __restrict__ uhs,
              const float* __restrict__ h,
              const float* __restrict__ Ww,
              const float* __restrict__ Wb,
              const float* __restrict__ Aw,
              const float* __restrict__ Ab,
              const int* __restrict__ captions,
              const float* __restrict__ emb,
              const float* __restrict__ bcat,
              float* __restrict__ incat,
              float* __restrict__ gates,
              float* __restrict__ alpha_out,   // out + ALPHA_OFF + t*NF
              int t) {
    const int b = blockIdx.x;
    const int tid = threadIdx.x;
    const int warp = tid >> 5;
    const int lane = tid & 31;

    __shared__ float s_h[DEC];
    __shared__ float s_wah[ATT];
    __shared__ float s_Aw[ATT];
    __shared__ float s_sc[NF];
    __shared__ float s_red[8];

    for (int i = tid; i < DEC; i += 256) s_h[i] = h[b * DEC + i];
    for (int i = tid; i < ATT; i += 256) s_Aw[i] = Aw[i];
    __syncthreads();

    // glue writes that don't depend on wah/scores
    {
        int tok = captions[b * (TSTEPS + 1) + t];
        for (int i = tid; i < EMB; i += 256)
            incat[(size_t)b * KCAT + i] = emb[(size_t)tok * EMB + i];
        for (int i = tid; i < DEC; i += 256)
            incat[(size_t)b * KCAT + EMB + ENC + i] = s_h[i];
        for (int i = tid; i < GATES4; i += 256)
            gates[(size_t)b * GATES4 + i] = bcat[i];
    }

    // wah[a] = Wb[a] + sum_d s_h[d] * Ww[d*ATT + a]
    for (int a = tid; a < ATT; a += 256) {
        float a0 = Wb[a], a1 = 0.f;
        #pragma unroll 4
        for (int d = 0; d < DEC; d += 2) {
            a0 += s_h[d]     * Ww[(size_t)d * ATT + a];
            a1 += s_h[d + 1] * Ww[(size_t)(d + 1) * ATT + a];
        }
        s_wah[a] = a0 + a1;
    }
    __syncthreads();

    const float Ab0 = Ab[0];
    // scores: 4 independent accumulator chains to hide tanh latency
    for (int f = warp; f < NF; f += 8) {
        const float* u = uhs + ((size_t)(b * NF + f)) * ATT;
        float a0 = 0.f, a1 = 0.f, a2 = 0.f, a3 = 0.f;
        #pragma unroll
        for (int k = lane; k < ATT; k += 128) {
            a0 += tanhf(u[k]       + s_wah[k])       * s_Aw[k];
            a1 += tanhf(u[k + 32]  + s_wah[k + 32])  * s_Aw[k + 32];
            a2 += tanhf(u[k + 64]  + s_wah[k + 64])  * s_Aw[k + 64];
            a3 += tanhf(u[k + 96]  + s_wah[k + 96])  * s_Aw[k + 96];
        }
        float acc = (a0 + a1) + (a2 + a3);
        #pragma unroll
        for (int o = 16; o; o >>= 1) acc += __shfl_xor_sync(0xffffffffu, acc, o);
        if (lane == 0) s_sc[f] = acc + Ab0;
    }
    __syncthreads();

    // softmax over NF
    float v = (tid < NF) ? s_sc[tid] : -1e30f;
    float m = v;
    #pragma unroll
    for (int o = 16; o; o >>= 1) m = fmaxf(m, __shfl_xor_sync(0xffffffffu, m, o));
    if (lane == 0) s_red[warp] = m;
    __syncthreads();
    if (tid == 0) {
        float mm = s_red[0];
        #pragma unroll
        for (int w = 1; w < 8; ++w) mm = fmaxf(mm, s_red[w]);
        s_red[0] = mm;
    }
    __syncthreads();
    const float mx = s_red[0];
    __syncthreads();
    float e = (tid < NF) ? expf(v - mx) : 0.f;
    float s = e;
    #pragma unroll
    for (int o = 16; o; o >>= 1) s += __shfl_xor_sync(0xffffffffu, s, o);
    if (lane == 0) s_red[warp] = s;
    __syncthreads();
    if (tid == 0) {
        float ss = 0.f;
        #pragma unroll
        for (int w = 0; w < 8; ++w) ss += s_red[w];
        s_red[0] = ss;
    }
    __syncthreads();
    const float inv_denom = 1.0f / s_red[0];
    if (tid < NF)
        alpha_out[(size_t)b * (TSTEPS * NF) + tid] = e * inv_denom;
}

// ---------------- context kernel: ctx[b,e] = sum_f alpha[b,f] * features[b,f,e] ----
// grid (ENC/256, B), 256 threads; writes into incat ctx slot
__global__ void __launch_bounds__(256)
context_kernel(const float* __restrict__ alphas,  // out + ALPHA_OFF + t*NF
               const float* __restrict__ features,
               float* __restrict__ incat) {
    const int b = blockIdx.y;
    const int tid = threadIdx.x;
    const int e = blockIdx.x * 256 + tid;

    __shared__ float s_a[NF];
    if (tid < NF) s_a[tid] = alphas[(size_t)b * (TSTEPS * NF) + tid];
    __syncthreads();

    const float* fp = features + (size_t)b * NF * ENC + e;
    float a0 = 0.f, a1 = 0.f, a2 = 0.f, a3 = 0.f;
    #pragma unroll
    for (int f = 0; f < NF - 3; f += 4) {
        a0 += s_a[f]     * fp[(size_t)f * ENC];
        a1 += s_a[f + 1] * fp[(size_t)(f + 1) * ENC];
        a2 += s_a[f + 2] * fp[(size_t)(f + 2) * ENC];
        a3 += s_a[f + 3] * fp[(size_t)(f + 3) * ENC];
    }
    incat[(size_t)b * KCAT + EMB + e] = ((a0 + a1) + (a2 + a3));
}

// ---------------- LSTM pointwise ----------------
__global__ void lstm_kernel(const float* __restrict__ gates,
                            float* __restrict__ h,
                            float* __restrict__ c) {
    int idx = blockIdx.x * blockDim.x + threadIdx.x;
    if (idx >= B * DEC) return;
    int b = idx / DEC;
    int n = idx - b * DEC;
    const float* g = gates + (size_t)b * GATES4;
    float i_ = g[n];
    float f_ = g[DEC + n];
    float gg = g[2 * DEC + n];
    float o_ = g[3 * DEC + n];
    float cc = c[idx];
    cc = sigmoidf_(f_) * cc + sigmoidf_(i_) * tanhf(gg);
    c[idx] = cc;
    h[idx] = sigmoidf_(o_) * tanhf(cc);
}

// ---------------- launch ----------------
extern "C" void kernel_launch(void* const* d_in, const int* in_sizes, int n_in,
                              void* d_out, int out_size) {
    const float* features = (const float*)d_in[0];
    const int*   captions = (const int*)  d_in[1];
    const float* emb      = (const float*)d_in[2];
    const float* Uw       = (const float*)d_in[3];
    const float* Ub       = (const float*)d_in[4];
    const float* Ww       = (const float*)d_in[5];
    const float* Wb       = (const float*)d_in[6];
    const float* Aw       = (const float*)d_in[7];
    const float* Ab       = (const float*)d_in[8];
    const float* ih_w     = (const float*)d_in[9];
    const float* ih_b     = (const float*)d_in[10];
    const float* ic_w     = (const float*)d_in[11];
    const float* ic_b     = (const float*)d_in[12];
    const float* W_ih     = (const float*)d_in[13];
    const float* b_ih     = (const float*)d_in[14];
    const float* W_hh     = (const float*)d_in[15];
    const float* b_hh     = (const float*)d_in[16];
    const float* fcn_w    = (const float*)d_in[17];
    const float* fcn_b    = (const float*)d_in[18];
    float* out = (float*)d_out;

    float* S = nullptr;
    cudaGetSymbolAddress((void**)&S, g_scratch);
    float* uhs   = S + OFF_UHS;
    float* Wcat  = S + OFF_WCAT;
    float* meanf = S + OFF_MEANF;
    float* h     = S + OFF_H;
    float* c     = S + OFF_C;
    float* incat = S + OFF_INCAT;
    float* gates = S + OFF_GATES;
    float* bcat  = S + OFF_BCAT;

    // ---- prep (ordered so ncu -s 5 -c 1 captures the uhs GEMM) ----
    prep_wcat_kernel<<<2048, 256>>>(W_ih, W_hh, b_ih, b_hh, Wcat, bcat);      // 1
    meanf_kernel<<<(B * ENC + 255) / 256, 256>>>(features, meanf);            // 2
    init_rows_kernel<<<(B * DEC + 255) / 256, 256>>>(h, ih_b, B * DEC, DEC);  // 3
    init_rows_kernel<<<(B * DEC + 255) / 256, 256>>>(c, ic_b, B * DEC, DEC);  // 4
    // h0 = meanf @ ih_w (+bias already), K-split 8                           // 5
    tf32_gemm<true><<<dim3(DEC / 128, 1, 8), 256>>>(meanf, ENC, ih_w, DEC, h, DEC,
                                                    nullptr, B, DEC, ENC);
    // u_hs = features @ Uw + Ub  (12544 x 512 x 2048)                        // 6
    tf32_gemm<false><<<dim3(ATT / 128, (B * NF) / 64, 1), 256>>>(
        features, ENC, Uw, ATT, uhs, ATT, Ub, B * NF, ATT, ENC);
    // c0 = meanf @ ic_w (+bias already)                                      // 7
    tf32_gemm<true><<<dim3(DEC / 128, 1, 8), 256>>>(meanf, ENC, ic_w, DEC, c, DEC,
                                                    nullptr, B, DEC, ENC);

    // ---- recurrent steps ----
    for (int t = 0; t < TSTEPS; ++t) {
        float* alpha_t = out + ALPHA_OFF + (size_t)t * NF;
        scores_kernel<<<B, 256>>>(uhs, h, Ww, Wb, Aw, Ab, captions, emb, bcat,
                                  incat, gates, alpha_t, t);
        context_kernel<<<dim3(ENC / 256, B), 256>>>(alpha_t, features, incat);
        // gates += incat @ Wcat  (64 x 2048 x 3072), K-split 8
        tf32_gemm<true><<<dim3(GATES4 / 128, 1, 8), 256>>>(incat, KCAT, Wcat, GATES4,
                                                           gates, GATES4, nullptr,
                                                           B, GATES4, KCAT);
        lstm_kernel<<<(B * DEC + 255) / 256, 256>>>(gates, h, c);
        // preds_t = h @ fcn_w + fcn_b  (64 x 30000 x 512)
        tf32_gemm<false><<<dim3((VOC + 127) / 128, 1, 1), 256>>>(
            h, DEC, fcn_w, VOC, out + (size_t)t * VOC, TSTEPS * VOC, fcn_b,
            B, VOC, DEC);
    }
}

// round 4
// speedup vs baseline: 3.1419x; 1.3924x over previous
#include <cuda_runtime.h>
#include <math.h>
#include <stdint.h>

// ---------------- problem constants ----------------
#define B    64
#define NF   196
#define ENC  2048
#define DEC  512
#define ATT  512
#define VOC  30000
#define EMB  512
#define TSTEPS 24
#define KCAT (EMB + ENC + DEC)   // 3072
#define GATES4 (4*DEC)           // 2048
#define N2   (VOC + ATT)         // 30512 combined output width

#define ALPHA_OFF ((size_t)B * TSTEPS * VOC)

// ---------------- scratch ----------------
#define OFF_UHS    ((size_t)0)                                  // 6,422,528
#define OFF_WCAT   (OFF_UHS   + (size_t)B*NF*ATT)               // 6,291,456
#define OFF_W2     (OFF_WCAT  + (size_t)KCAT*GATES4)            // 15,622,144
#define OFF_FEATR  (OFF_W2    + (size_t)DEC*N2)                 // 25,690,112
#define OFF_IHR    (OFF_FEATR + (size_t)B*NF*ENC)               // 1,048,576
#define OFF_ICR    (OFF_IHR   + (size_t)ENC*DEC)
#define OFF_UWR    (OFF_ICR   + (size_t)ENC*DEC)
#define OFF_MEANF  (OFF_UWR   + (size_t)ENC*ATT)                // 131,072
#define OFF_H      (OFF_MEANF + (size_t)B*ENC)
#define OFF_C      (OFF_H     + (size_t)B*DEC)
#define OFF_HR     (OFF_C     + (size_t)B*DEC)
#define OFF_WAH    (OFF_HR    + (size_t)B*DEC)
#define OFF_INCAT  (OFF_WAH   + (size_t)B*ATT)
#define OFF_GATES  (OFF_INCAT + (size_t)B*KCAT)
#define OFF_BCAT   (OFF_GATES + (size_t)B*GATES4)
#define SCRATCH_TOTAL (OFF_BCAT + (size_t)GATES4)

__device__ __align__(16) float g_scratch[SCRATCH_TOTAL];

__device__ __forceinline__ float sigmoidf_(float x) {
    return 1.0f / (1.0f + expf(-x));
}
__device__ __forceinline__ float f2tf_f(float x) {
    uint32_t r;
    asm("cvt.rna.tf32.f32 %0, %1;" : "=r"(r) : "f"(x));
    return __uint_as_float(r);
}

// ---------------- prep: Wcat = round([W_ih ; W_hh]), bcat ----------------
__global__ void prep_wcat_kernel(const float* __restrict__ W_ih,
                                 const float* __restrict__ W_hh,
                                 const float* __restrict__ b_ih,
                                 const float* __restrict__ b_hh,
                                 float* __restrict__ Wcat,
                                 float* __restrict__ bcat) {
    int total = KCAT * GATES4;
    for (int i = blockIdx.x * blockDim.x + threadIdx.x; i < total;
         i += gridDim.x * blockDim.x) {
        int r = i / GATES4;
        int c = i - r * GATES4;
        float v = (r < EMB + ENC) ? W_ih[i] : W_hh[(r - (EMB + ENC)) * GATES4 + c];
        Wcat[i] = f2tf_f(v);
    }
    int idx = blockIdx.x * blockDim.x + threadIdx.x;
    if (idx < GATES4) bcat[idx] = b_ih[idx] + b_hh[idx];
}

// ---------------- prep: W2 = round([fcn_w | Ww])  (DEC x N2) ----------------
__global__ void prep_w2_kernel(const float* __restrict__ fcn_w,
                               const float* __restrict__ Ww,
                               float* __restrict__ W2) {
    int total = DEC * N2;
    for (int i = blockIdx.x * blockDim.x + threadIdx.x; i < total;
         i += gridDim.x * blockDim.x) {
        int k = i / N2;
        int c = i - k * N2;
        float v = (c < VOC) ? fcn_w[(size_t)k * VOC + c]
                            : Ww[(size_t)k * ATT + (c - VOC)];
        W2[i] = f2tf_f(v);
    }
}

// ---------------- generic round-copy ----------------
__global__ void round_copy_kernel(const float* __restrict__ src,
                                  float* __restrict__ dst, int n) {
    for (int i = blockIdx.x * blockDim.x + threadIdx.x; i < n;
         i += gridDim.x * blockDim.x)
        dst[i] = f2tf_f(src[i]);
}

// ---------------- mean over NF (rounded output) ----------------
__global__ void meanf_kernel(const float* __restrict__ features,
                             float* __restrict__ meanf) {
    int idx = blockIdx.x * blockDim.x + threadIdx.x;
    if (idx < B * ENC) {
        int b = idx >> 11;
        int e = idx & (ENC - 1);
        const float* p = features + (size_t)b * NF * ENC + e;
        float s0 = 0.f, s1 = 0.f, s2 = 0.f, s3 = 0.f;
        int f = 0;
        #pragma unroll 1
        for (; f + 4 <= NF; f += 4) {
            s0 += p[(size_t)(f + 0) * ENC];
            s1 += p[(size_t)(f + 1) * ENC];
            s2 += p[(size_t)(f + 2) * ENC];
            s3 += p[(size_t)(f + 3) * ENC];
        }
        for (; f < NF; ++f) s0 += p[(size_t)f * ENC];
        meanf[idx] = f2tf_f(((s0 + s1) + (s2 + s3)) * (1.0f / (float)NF));
    }
}

// ---------------- init rows with bias ----------------
__global__ void init_rows_kernel(float* __restrict__ C,
                                 const float* __restrict__ bias,
                                 int total, int cols) {
    int i = blockIdx.x * blockDim.x + threadIdx.x;
    if (i < total) C[i] = bias[i % cols];
}

// ---------------- tf32 tensor-core GEMM ----------------
// C(M,N) = A(M,K) @ B(K,N). All operands PRE-ROUNDED to tf32 bit patterns.
// block tile 64x128, 8 warps (2M x 4N), warp 32x32, mma.m16n8k8.tf32.
// B double-buffered via cp.async; A staged into fragment-ready smem layout.
// MODE 0: atomicAdd into pre-initialized C (K-split via gridDim.z)
// MODE 1: C = acc + bias
// MODE 2: split epilogue: col < Ncut -> C (+bias), else -> C2 (+bias2), ldc2
// Requirements: m0+64 <= M, K % (32*gridDim.z) == 0, N % 4 == 0, ldb % 4 == 0.
template <int MODE>
__global__ void __launch_bounds__(256)
tf32_gemm(const float* __restrict__ A, int lda,
          const float* __restrict__ Bm, int ldb,
          float* __restrict__ C, int ldc,
          const float* __restrict__ bias,
          float* __restrict__ C2, int ldc2,
          const float* __restrict__ bias2,
          int M, int N, int K, int Ncut) {
    __shared__ __align__(16) float Af[2048];          // frag layout, 8 KB
    __shared__ __align__(16) float Bs[2][32][136];    // 34.8 KB

    const int tid  = threadIdx.x;
    const int lane = tid & 31;
    const int warp = tid >> 5;
    const int wm = warp >> 2;
    const int wn = warp & 3;
    const int g = lane >> 2;
    const int t = lane & 3;

    const int m0 = blockIdx.y * 64;
    const int n0 = blockIdx.x * 128;
    const int chunks = (K / 32) / gridDim.z;
    const int kc0 = blockIdx.z * chunks;

    const int arow = tid >> 3;           // 0..31
    const int ac4  = (tid & 7) * 4;      // 0..28

    // fragment-store addresses for the two A rows this thread stages
    // e = (row&8 ? 1:0) + (kk&4 ? 2:0); ks = ac4>>3; t = j
    const int ksA = ac4 >> 3;
    const int eA  = (ac4 & 4) ? 2 : 0;
    const int r1 = arow, r2 = arow + 32;
    const int mt1 = r1 >> 4, mt2 = r2 >> 4;
    const int g1 = r1 & 7;               // same as r2&7
    const int e1 = eA + ((r1 >> 3) & 1);
    const int e2 = eA + ((r2 >> 3) & 1);
    const int base1 = ((mt1 * 4 + ksA) * 32 + g1 * 4) * 4 + e1;
    const int base2 = ((mt2 * 4 + ksA) * 32 + g1 * 4) * 4 + e2;

    float acc[2][4][4];
    #pragma unroll
    for (int mi = 0; mi < 2; ++mi)
        #pragma unroll
        for (int ni = 0; ni < 4; ++ni)
            #pragma unroll
            for (int q = 0; q < 4; ++q) acc[mi][ni][q] = 0.f;

    float4 areg0, areg1;

    // ---- prologue
    {
        const int k0 = kc0 * 32;
        areg0 = *reinterpret_cast<const float4*>(A + (size_t)(m0 + r1) * lda + k0 + ac4);
        areg1 = *reinterpret_cast<const float4*>(A + (size_t)(m0 + r2) * lda + k0 + ac4);
        #pragma unroll
        for (int i = 0; i < 4; ++i) {
            int j = tid + i * 256;
            int r = j >> 5;
            int c4 = (j & 31) * 4;
            int col = n0 + c4;
            const float* src = Bm + (size_t)(k0 + r) * ldb + (col < N ? col : 0);
            uint32_t saddr = (uint32_t)__cvta_generic_to_shared(&Bs[0][r][c4]);
            int sz = (col < N) ? 16 : 0;
            asm volatile("cp.async.cg.shared.global [%0], [%1], 16, %2;\n"
                         :: "r"(saddr), "l"(src), "r"(sz));
        }
        asm volatile("cp.async.commit_group;\n");
        Af[base1 + 0]  = areg0.x; Af[base1 + 4]  = areg0.y;
        Af[base1 + 8]  = areg0.z; Af[base1 + 12] = areg0.w;
        Af[base2 + 0]  = areg1.x; Af[base2 + 4]  = areg1.y;
        Af[base2 + 8]  = areg1.z; Af[base2 + 12] = areg1.w;
    }

    for (int cc = 0; cc < chunks; ++cc) {
        const int st = cc & 1;
        if (cc + 1 < chunks) {
            const int k0 = (kc0 + cc + 1) * 32;
            #pragma unroll
            for (int i = 0; i < 4; ++i) {
                int j = tid + i * 256;
                int r = j >> 5;
                int c4 = (j & 31) * 4;
                int col = n0 + c4;
                const float* src = Bm + (size_t)(k0 + r) * ldb + (col < N ? col : 0);
                uint32_t saddr = (uint32_t)__cvta_generic_to_shared(&Bs[st ^ 1][r][c4]);
                int sz = (col < N) ? 16 : 0;
                asm volatile("cp.async.cg.shared.global [%0], [%1], 16, %2;\n"
                             :: "r"(saddr), "l"(src), "r"(sz));
            }
            areg0 = *reinterpret_cast<const float4*>(A + (size_t)(m0 + r1) * lda + k0 + ac4);
            areg1 = *reinterpret_cast<const float4*>(A + (size_t)(m0 + r2) * lda + k0 + ac4);
        }
        asm volatile("cp.async.commit_group;\n");
        asm volatile("cp.async.wait_group 1;\n");
        __syncthreads();

        #pragma unroll
        for (int ks = 0; ks < 4; ++ks) {
            const int k8 = ks * 8;
            uint32_t af[2][4];
            #pragma unroll
            for (int mi = 0; mi < 2; ++mi) {
                int mt = wm * 2 + mi;
                float4 a = *reinterpret_cast<const float4*>(
                    &Af[((mt * 4 + ks) * 32 + lane) * 4]);
                af[mi][0] = __float_as_uint(a.x);
                af[mi][1] = __float_as_uint(a.y);
                af[mi][2] = __float_as_uint(a.z);
                af[mi][3] = __float_as_uint(a.w);
            }
            #pragma unroll
            for (int ni = 0; ni < 4; ++ni) {
                int cB = wn * 32 + ni * 8 + g;
                uint32_t b0 = __float_as_uint(Bs[st][k8 + t][cB]);
                uint32_t b1 = __float_as_uint(Bs[st][k8 + t + 4][cB]);
                #pragma unroll
                for (int mi = 0; mi < 2; ++mi) {
                    asm volatile(
                        "mma.sync.aligned.m16n8k8.row.col.f32.tf32.tf32.f32 "
                        "{%0,%1,%2,%3}, {%4,%5,%6,%7}, {%8,%9}, {%0,%1,%2,%3};"
                        : "+f"(acc[mi][ni][0]), "+f"(acc[mi][ni][1]),
                          "+f"(acc[mi][ni][2]), "+f"(acc[mi][ni][3])
                        : "r"(af[mi][0]), "r"(af[mi][1]),
                          "r"(af[mi][2]), "r"(af[mi][3]),
                          "r"(b0), "r"(b1));
                }
            }
        }
        __syncthreads();
        if (cc + 1 < chunks) {
            Af[base1 + 0]  = areg0.x; Af[base1 + 4]  = areg0.y;
            Af[base1 + 8]  = areg0.z; Af[base1 + 12] = areg0.w;
            Af[base2 + 0]  = areg1.x; Af[base2 + 4]  = areg1.y;
            Af[base2 + 8]  = areg1.z; Af[base2 + 12] = areg1.w;
        }
    }

    // epilogue: c0:(g,2t) c1:(g,2t+1) c2:(g+8,2t) c3:(g+8,2t+1)
    #pragma unroll
    for (int mi = 0; mi < 2; ++mi) {
        int r0 = m0 + wm * 32 + mi * 16 + g;
        #pragma unroll
        for (int ni = 0; ni < 4; ++ni) {
            int col = n0 + wn * 32 + ni * 8 + 2 * t;
            if (col >= N) continue;
            if (MODE == 0) {
                atomicAdd(&C[(size_t)r0 * ldc + col],           acc[mi][ni][0]);
                atomicAdd(&C[(size_t)r0 * ldc + col + 1],       acc[mi][ni][1]);
                atomicAdd(&C[(size_t)(r0 + 8) * ldc + col],     acc[mi][ni][2]);
                atomicAdd(&C[(size_t)(r0 + 8) * ldc + col + 1], acc[mi][ni][3]);
            } else if (MODE == 1) {
                float bv0 = bias ? bias[col] : 0.f;
                float bv1 = bias ? bias[col + 1] : 0.f;
                float2 v0 = make_float2(acc[mi][ni][0] + bv0, acc[mi][ni][1] + bv1);
                float2 v1 = make_float2(acc[mi][ni][2] + bv0, acc[mi][ni][3] + bv1);
                *reinterpret_cast<float2*>(&C[(size_t)r0 * ldc + col]) = v0;
                *reinterpret_cast<float2*>(&C[(size_t)(r0 + 8) * ldc + col]) = v1;
            } else {
                if (col < Ncut) {
                    float bv0 = bias[col], bv1 = bias[col + 1];
                    float2 v0 = make_float2(acc[mi][ni][0] + bv0, acc[mi][ni][1] + bv1);
                    float2 v1 = make_float2(acc[mi][ni][2] + bv0, acc[mi][ni][3] + bv1);
                    *reinterpret_cast<float2*>(&C[(size_t)r0 * ldc + col]) = v0;
                    *reinterpret_cast<float2*>(&C[(size_t)(r0 + 8) * ldc + col]) = v1;
                } else {
                    int c2 = col - Ncut;
                    float bv0 = bias2[c2], bv1 = bias2[c2 + 1];
                    float2 v0 = make_float2(acc[mi][ni][0] + bv0, acc[mi][ni][1] + bv1);
                    float2 v1 = make_float2(acc[mi][ni][2] + bv0, acc[mi][ni][3] + bv1);
                    *reinterpret_cast<float2*>(&C2[(size_t)r0 * ldc2 + c2]) = v0;
                    *reinterpret_cast<float2*>(&C2[(size_t)(r0 + 8) * ldc2 + c2]) = v1;
                }
            }
        }
    }
}

// ---------------- scores kernel: scores + softmax + glue ----------------
__global__ void __launch_bounds__(256)
scores_kernel(const float* __restrict__ uhs,
              const float* __restrict__ wah,
              const float* __restrict__ Aw,
              const float* __restrict__ Ab,
              const int* __restrict__ captions,
              const float* __restrict__ emb,
              const float* __restrict__ bcat,
              const float* __restrict__ hr,
              float* __restrict__ incat,
              float* __restrict__ gates,
              float* __restrict__ alpha_out,
              int t) {
    const int b = blockIdx.x;
    const int tid = threadIdx.x;
    const int warp = tid >> 5;
    const int lane = tid & 31;

    __shared__ float s_wah[ATT];
    __shared__ float s_Aw[ATT];
    __shared__ float s_sc[NF];
    __shared__ float s_red[8];

    for (int i = tid; i < ATT; i += 256) {
        s_wah[i] = wah[b * ATT + i];
        s_Aw[i]  = Aw[i];
    }
    __syncthreads();

    // glue (independent of scores)
    {
        int tok = captions[b * (TSTEPS + 1) + t];
        for (int i = tid; i < EMB; i += 256)
            incat[(size_t)b * KCAT + i] = f2tf_f(emb[(size_t)tok * EMB + i]);
        for (int i = tid; i < DEC; i += 256)
            incat[(size_t)b * KCAT + EMB + ENC + i] = hr[b * DEC + i];
        for (int i = tid; i < GATES4; i += 256)
            gates[(size_t)b * GATES4 + i] = bcat[i];
    }

    const float Ab0 = Ab[0];
    for (int f = warp; f < NF; f += 8) {
        const float* u = uhs + ((size_t)(b * NF + f)) * ATT;
        float a0 = 0.f, a1 = 0.f, a2 = 0.f, a3 = 0.f;
        #pragma unroll
        for (int k = lane; k < ATT; k += 128) {
            a0 += tanhf(u[k]      + s_wah[k])      * s_Aw[k];
            a1 += tanhf(u[k + 32] + s_wah[k + 32]) * s_Aw[k + 32];
            a2 += tanhf(u[k + 64] + s_wah[k + 64]) * s_Aw[k + 64];
            a3 += tanhf(u[k + 96] + s_wah[k + 96]) * s_Aw[k + 96];
        }
        float acc = (a0 + a1) + (a2 + a3);
        #pragma unroll
        for (int o = 16; o; o >>= 1) acc += __shfl_xor_sync(0xffffffffu, acc, o);
        if (lane == 0) s_sc[f] = acc + Ab0;
    }
    __syncthreads();

    float v = (tid < NF) ? s_sc[tid] : -1e30f;
    float m = v;
    #pragma unroll
    for (int o = 16; o; o >>= 1) m = fmaxf(m, __shfl_xor_sync(0xffffffffu, m, o));
    if (lane == 0) s_red[warp] = m;
    __syncthreads();
    if (tid == 0) {
        float mm = s_red[0];
        #pragma unroll
        for (int w = 1; w < 8; ++w) mm = fmaxf(mm, s_red[w]);
        s_red[0] = mm;
    }
    __syncthreads();
    const float mx = s_red[0];
    __syncthreads();
    float e = (tid < NF) ? expf(v - mx) : 0.f;
    float s = e;
    #pragma unroll
    for (int o = 16; o; o >>= 1) s += __shfl_xor_sync(0xffffffffu, s, o);
    if (lane == 0) s_red[warp] = s;
    __syncthreads();
    if (tid == 0) {
        float ss = 0.f;
        #pragma unroll
        for (int w = 0; w < 8; ++w) ss += s_red[w];
        s_red[0] = ss;
    }
    __syncthreads();
    const float inv_denom = 1.0f / s_red[0];
    if (tid < NF)
        alpha_out[(size_t)b * (TSTEPS * NF) + tid] = e * inv_denom;
}

// ---------------- context kernel (rounded write into incat ctx slot) -------
__global__ void __launch_bounds__(256)
context_kernel(const float* __restrict__ alphas,
               const float* __restrict__ features,
               float* __restrict__ incat) {
    const int b = blockIdx.y;
    const int tid = threadIdx.x;
    const int e = blockIdx.x * 256 + tid;

    __shared__ float s_a[NF];
    if (tid < NF) s_a[tid] = alphas[(size_t)b * (TSTEPS * NF) + tid];
    __syncthreads();

    const float* fp = features + (size_t)b * NF * ENC + e;
    float a0 = 0.f, a1 = 0.f, a2 = 0.f, a3 = 0.f;
    #pragma unroll
    for (int f = 0; f < NF - 3; f += 4) {
        a0 += s_a[f]     * fp[(size_t)f * ENC];
        a1 += s_a[f + 1] * fp[(size_t)(f + 1) * ENC];
        a2 += s_a[f + 2] * fp[(size_t)(f + 2) * ENC];
        a3 += s_a[f + 3] * fp[(size_t)(f + 3) * ENC];
    }
    incat[(size_t)b * KCAT + EMB + e] = f2tf_f((a0 + a1) + (a2 + a3));
}

// ---------------- LSTM pointwise (writes rounded hr) ----------------
__global__ void lstm_kernel(const float* __restrict__ gates,
                            float* __restrict__ hr,
                            float* __restrict__ c) {
    int idx = blockIdx.x * blockDim.x + threadIdx.x;
    if (idx >= B * DEC) return;
    int b = idx / DEC;
    int n = idx - b * DEC;
    const float* g = gates + (size_t)b * GATES4;
    float i_ = g[n];
    float f_ = g[DEC + n];
    float gg = g[2 * DEC + n];
    float o_ = g[3 * DEC + n];
    float cc = c[idx];
    cc = sigmoidf_(f_) * cc + sigmoidf_(i_) * tanhf(gg);
    c[idx] = cc;
    hr[idx] = f2tf_f(sigmoidf_(o_) * tanhf(cc));
}

// ---------------- launch ----------------
extern "C" void kernel_launch(void* const* d_in, const int* in_sizes, int n_in,
                              void* d_out, int out_size) {
    const float* features = (const float*)d_in[0];
    const int*   captions = (const int*)  d_in[1];
    const float* emb      = (const float*)d_in[2];
    const float* Uw       = (const float*)d_in[3];
    const float* Ub       = (const float*)d_in[4];
    const float* Ww       = (const float*)d_in[5];
    const float* Wb       = (const float*)d_in[6];
    const float* Aw       = (const float*)d_in[7];
    const float* Ab       = (const float*)d_in[8];
    const float* ih_w     = (const float*)d_in[9];
    const float* ih_b     = (const float*)d_in[10];
    const float* ic_w     = (const float*)d_in[11];
    const float* ic_b     = (const float*)d_in[12];
    const float* W_ih     = (const float*)d_in[13];
    const float* b_ih     = (const float*)d_in[14];
    const float* W_hh     = (const float*)d_in[15];
    const float* b_hh     = (const float*)d_in[16];
    const float* fcn_w    = (const float*)d_in[17];
    const float* fcn_b    = (const float*)d_in[18];
    float* out = (float*)d_out;

    float* S = nullptr;
    cudaGetSymbolAddress((void**)&S, g_scratch);
    float* uhs   = S + OFF_UHS;
    float* Wcat  = S + OFF_WCAT;
    float* W2    = S + OFF_W2;
    float* featr = S + OFF_FEATR;
    float* ihr   = S + OFF_IHR;
    float* icr   = S + OFF_ICR;
    float* uwr   = S + OFF_UWR;
    float* meanf = S + OFF_MEANF;
    float* h     = S + OFF_H;
    float* c     = S + OFF_C;
    float* hr    = S + OFF_HR;
    float* wah   = S + OFF_WAH;
    float* incat = S + OFF_INCAT;
    float* gates = S + OFF_GATES;
    float* bcat  = S + OFF_BCAT;

    // ---- prep ----
    prep_wcat_kernel<<<2048, 256>>>(W_ih, W_hh, b_ih, b_hh, Wcat, bcat);
    prep_w2_kernel<<<2048, 256>>>(fcn_w, Ww, W2);
    round_copy_kernel<<<2048, 256>>>(features, featr, B * NF * ENC);
    round_copy_kernel<<<512, 256>>>(ih_w, ihr, ENC * DEC);
    round_copy_kernel<<<512, 256>>>(ic_w, icr, ENC * DEC);
    round_copy_kernel<<<512, 256>>>(Uw, uwr, ENC * ATT);
    meanf_kernel<<<(B * ENC + 255) / 256, 256>>>(features, meanf);
    init_rows_kernel<<<(B * DEC + 255) / 256, 256>>>(h, ih_b, B * DEC, DEC);
    init_rows_kernel<<<(B * DEC + 255) / 256, 256>>>(c, ic_b, B * DEC, DEC);
    // h0 = meanf @ ih_r (+bias), K-split 8
    tf32_gemm<0><<<dim3(DEC / 128, 1, 8), 256>>>(meanf, ENC, ihr, DEC, h, DEC,
        nullptr, nullptr, 0, nullptr, B, DEC, ENC, 0);
    tf32_gemm<0><<<dim3(DEC / 128, 1, 8), 256>>>(meanf, ENC, icr, DEC, c, DEC,
        nullptr, nullptr, 0, nullptr, B, DEC, ENC, 0);
    round_copy_kernel<<<(B * DEC + 255) / 256, 256>>>(h, hr, B * DEC);
    // wah0 = hr @ Ww (+Wb); Ww region of W2 at column offset VOC
    init_rows_kernel<<<(B * ATT + 255) / 256, 256>>>(wah, Wb, B * ATT, ATT);
    tf32_gemm<0><<<dim3(ATT / 128, 1, 4), 256>>>(hr, DEC, W2 + VOC, N2, wah, ATT,
        nullptr, nullptr, 0, nullptr, B, ATT, DEC, 0);
    // u_hs = featr @ uwr + Ub  (12544 x 512 x 2048)
    tf32_gemm<1><<<dim3(ATT / 128, (B * NF) / 64, 1), 256>>>(featr, ENC, uwr, ATT,
        uhs, ATT, Ub, nullptr, 0, nullptr, B * NF, ATT, ENC, 0);

    // ---- recurrent steps ----
    for (int t = 0; t < TSTEPS; ++t) {
        float* alpha_t = out + ALPHA_OFF + (size_t)t * NF;
        scores_kernel<<<B, 256>>>(uhs, wah, Aw, Ab, captions, emb, bcat, hr,
                                  incat, gates, alpha_t, t);
        context_kernel<<<dim3(ENC / 256, B), 256>>>(alpha_t, features, incat);
        // gates += incat @ Wcat  (64 x 2048 x 3072), K-split 8
        tf32_gemm<0><<<dim3(GATES4 / 128, 1, 8), 256>>>(incat, KCAT, Wcat, GATES4,
            gates, GATES4, nullptr, nullptr, 0, nullptr, B, GATES4, KCAT, 0);
        lstm_kernel<<<(B * DEC + 255) / 256, 256>>>(gates, hr, c);
        // combined: [preds_t | wah_{t+1}] = hr @ W2 (+[fcn_b|Wb])
        tf32_gemm<2><<<dim3((N2 + 127) / 128, 1, 1), 256>>>(hr, DEC, W2, N2,
            out + (size_t)t * VOC, TSTEPS * VOC, fcn_b,
            wah, ATT, Wb, B, N2, DEC, VOC);
    }
}

// round 5
// speedup vs baseline: 3.9503x; 1.2573x over previous
#include <cuda_runtime.h>
#include <math.h>
#include <stdint.h>

// ---------------- problem constants ----------------
#define B    64
#define NF   196
#define ENC  2048
#define DEC  512
#define ATT  512
#define VOC  30000
#define EMB  512
#define TSTEPS 24
#define KCAT (EMB + ENC + DEC)   // 3072
#define GATES4 (4*DEC)           // 2048
#define N2   (VOC + ATT)         // 30512

#define ALPHA_OFF ((size_t)B * TSTEPS * VOC)

// ---------------- scratch ----------------
#define OFF_UHS    ((size_t)0)
#define OFF_WCAT   (OFF_UHS   + (size_t)B*NF*ATT)
#define OFF_W2     (OFF_WCAT  + (size_t)KCAT*GATES4)
#define OFF_IHR    (OFF_W2    + (size_t)DEC*N2)
#define OFF_ICR    (OFF_IHR   + (size_t)ENC*DEC)
#define OFF_UWR    (OFF_ICR   + (size_t)ENC*DEC)
#define OFF_MEANF  (OFF_UWR   + (size_t)ENC*ATT)
#define OFF_H      (OFF_MEANF + (size_t)B*ENC)
#define OFF_C      (OFF_H     + (size_t)B*DEC)
#define OFF_HR     (OFF_C     + (size_t)B*DEC)
#define OFF_WAH    (OFF_HR    + (size_t)B*DEC)
#define OFF_INCAT  (OFF_WAH   + (size_t)B*ATT)
#define OFF_GATES  (OFF_INCAT + (size_t)B*KCAT)
#define OFF_BCAT   (OFF_GATES + (size_t)B*GATES4)
#define SCRATCH_TOTAL (OFF_BCAT + (size_t)GATES4)

__device__ __align__(16) float g_scratch[SCRATCH_TOTAL];

__device__ __forceinline__ float sigmoidf_(float x) {
    return 1.0f / (1.0f + expf(-x));
}
__device__ __forceinline__ float f2tf_f(float x) {
    uint32_t r;
    asm("cvt.rna.tf32.f32 %0, %1;" : "=r"(r) : "f"(x));
    return __uint_as_float(r);
}
__device__ __forceinline__ float htanh(float x) {
    float y;
    asm("tanh.approx.f32 %0, %1;" : "=f"(y) : "f"(x));
    return y;
}

// ---------------- prep kernels ----------------
__global__ void prep_wcat_kernel(const float* __restrict__ W_ih,
                                 const float* __restrict__ W_hh,
                                 const float* __restrict__ b_ih,
                                 const float* __restrict__ b_hh,
                                 float* __restrict__ Wcat,
                                 float* __restrict__ bcat) {
    int total = KCAT * GATES4;
    for (int i = blockIdx.x * blockDim.x + threadIdx.x; i < total;
         i += gridDim.x * blockDim.x) {
        int r = i / GATES4;
        int c = i - r * GATES4;
        float v = (r < EMB + ENC) ? W_ih[i] : W_hh[(r - (EMB + ENC)) * GATES4 + c];
        Wcat[i] = f2tf_f(v);
    }
    int idx = blockIdx.x * blockDim.x + threadIdx.x;
    if (idx < GATES4) bcat[idx] = b_ih[idx] + b_hh[idx];
}

__global__ void prep_w2_kernel(const float* __restrict__ fcn_w,
                               const float* __restrict__ Ww,
                               float* __restrict__ W2) {
    int total = DEC * N2;
    for (int i = blockIdx.x * blockDim.x + threadIdx.x; i < total;
         i += gridDim.x * blockDim.x) {
        int k = i / N2;
        int c = i - k * N2;
        float v = (c < VOC) ? fcn_w[(size_t)k * VOC + c]
                            : Ww[(size_t)k * ATT + (c - VOC)];
        W2[i] = f2tf_f(v);
    }
}

__global__ void round_copy_kernel(const float* __restrict__ src,
                                  float* __restrict__ dst, int n) {
    for (int i = blockIdx.x * blockDim.x + threadIdx.x; i < n;
         i += gridDim.x * blockDim.x)
        dst[i] = f2tf_f(src[i]);
}

__global__ void meanf_kernel(const float* __restrict__ features,
                             float* __restrict__ meanf) {
    int idx = blockIdx.x * blockDim.x + threadIdx.x;
    if (idx < B * ENC) {
        int b = idx >> 11;
        int e = idx & (ENC - 1);
        const float* p = features + (size_t)b * NF * ENC + e;
        float s0 = 0.f, s1 = 0.f, s2 = 0.f, s3 = 0.f;
        int f = 0;
        #pragma unroll 1
        for (; f + 4 <= NF; f += 4) {
            s0 += p[(size_t)(f + 0) * ENC];
            s1 += p[(size_t)(f + 1) * ENC];
            s2 += p[(size_t)(f + 2) * ENC];
            s3 += p[(size_t)(f + 3) * ENC];
        }
        for (; f < NF; ++f) s0 += p[(size_t)f * ENC];
        meanf[idx] = f2tf_f(((s0 + s1) + (s2 + s3)) * (1.0f / (float)NF));
    }
}

// ---------------- tf32 tensor-core GEMM ----------------
// C(M,N) = A(M,K) @ B(K,N). B operand must be pre-rounded tf32 bits.
// A pre-rounded unless CVTA=true (then rounded during smem staging).
// block 64x128, 8 warps, warp 32x32, mma.m16n8k8, cp.async double-buffered B.
// MODE 0: atomicAdd into pre-initialized C (K-split via gridDim.z)
// MODE 1: C = acc + bias
// MODE 2: col < Ncut -> C (+bias), else -> C2 (+bias2)
template <int MODE, bool CVTA>
__global__ void __launch_bounds__(256)
tf32_gemm(const float* __restrict__ A, int lda,
          const float* __restrict__ Bm, int ldb,
          float* __restrict__ C, int ldc,
          const float* __restrict__ bias,
          float* __restrict__ C2, int ldc2,
          const float* __restrict__ bias2,
          int M, int N, int K, int Ncut) {
    __shared__ __align__(16) float Af[2048];
    __shared__ __align__(16) float Bs[2][32][136];

    const int tid  = threadIdx.x;
    const int lane = tid & 31;
    const int warp = tid >> 5;
    const int wm = warp >> 2;
    const int wn = warp & 3;
    const int g = lane >> 2;
    const int t = lane & 3;

    const int m0 = blockIdx.y * 64;
    const int n0 = blockIdx.x * 128;
    const int chunks = (K / 32) / gridDim.z;
    const int kc0 = blockIdx.z * chunks;

    const int arow = tid >> 3;
    const int ac4  = (tid & 7) * 4;

    const int ksA = ac4 >> 3;
    const int eA  = (ac4 & 4) ? 2 : 0;
    const int r1 = arow, r2 = arow + 32;
    const int mt1 = r1 >> 4, mt2 = r2 >> 4;
    const int g1 = r1 & 7;
    const int e1 = eA + ((r1 >> 3) & 1);
    const int e2 = eA + ((r2 >> 3) & 1);
    const int base1 = ((mt1 * 4 + ksA) * 32 + g1 * 4) * 4 + e1;
    const int base2 = ((mt2 * 4 + ksA) * 32 + g1 * 4) * 4 + e2;

    float acc[2][4][4];
    #pragma unroll
    for (int mi = 0; mi < 2; ++mi)
        #pragma unroll
        for (int ni = 0; ni < 4; ++ni)
            #pragma unroll
            for (int q = 0; q < 4; ++q) acc[mi][ni][q] = 0.f;

    float4 areg0, areg1;

    {
        const int k0 = kc0 * 32;
        areg0 = *reinterpret_cast<const float4*>(A + (size_t)(m0 + r1) * lda + k0 + ac4);
        areg1 = *reinterpret_cast<const float4*>(A + (size_t)(m0 + r2) * lda + k0 + ac4);
        #pragma unroll
        for (int i = 0; i < 4; ++i) {
            int j = tid + i * 256;
            int r = j >> 5;
            int c4 = (j & 31) * 4;
            int col = n0 + c4;
            const float* src = Bm + (size_t)(k0 + r) * ldb + (col < N ? col : 0);
            uint32_t saddr = (uint32_t)__cvta_generic_to_shared(&Bs[0][r][c4]);
            int sz = (col < N) ? 16 : 0;
            asm volatile("cp.async.cg.shared.global [%0], [%1], 16, %2;\n"
                         :: "r"(saddr), "l"(src), "r"(sz));
        }
        asm volatile("cp.async.commit_group;\n");
        if (CVTA) {
            areg0.x = f2tf_f(areg0.x); areg0.y = f2tf_f(areg0.y);
            areg0.z = f2tf_f(areg0.z); areg0.w = f2tf_f(areg0.w);
            areg1.x = f2tf_f(areg1.x); areg1.y = f2tf_f(areg1.y);
            areg1.z = f2tf_f(areg1.z); areg1.w = f2tf_f(areg1.w);
        }
        Af[base1 + 0]  = areg0.x; Af[base1 + 4]  = areg0.y;
        Af[base1 + 8]  = areg0.z; Af[base1 + 12] = areg0.w;
        Af[base2 + 0]  = areg1.x; Af[base2 + 4]  = areg1.y;
        Af[base2 + 8]  = areg1.z; Af[base2 + 12] = areg1.w;
    }

    for (int cc = 0; cc < chunks; ++cc) {
        const int st = cc & 1;
        if (cc + 1 < chunks) {
            const int k0 = (kc0 + cc + 1) * 32;
            #pragma unroll
            for (int i = 0; i < 4; ++i) {
                int j = tid + i * 256;
                int r = j >> 5;
                int c4 = (j & 31) * 4;
                int col = n0 + c4;
                const float* src = Bm + (size_t)(k0 + r) * ldb + (col < N ? col : 0);
                uint32_t saddr = (uint32_t)__cvta_generic_to_shared(&Bs[st ^ 1][r][c4]);
                int sz = (col < N) ? 16 : 0;
                asm volatile("cp.async.cg.shared.global [%0], [%1], 16, %2;\n"
                             :: "r"(saddr), "l"(src), "r"(sz));
            }
            areg0 = *reinterpret_cast<const float4*>(A + (size_t)(m0 + r1) * lda + k0 + ac4);
            areg1 = *reinterpret_cast<const float4*>(A + (size_t)(m0 + r2) * lda + k0 + ac4);
        }
        asm volatile("cp.async.commit_group;\n");
        asm volatile("cp.async.wait_group 1;\n");
        __syncthreads();

        #pragma unroll
        for (int ks = 0; ks < 4; ++ks) {
            const int k8 = ks * 8;
            uint32_t af[2][4];
            #pragma unroll
            for (int mi = 0; mi < 2; ++mi) {
                int mt = wm * 2 + mi;
                float4 a = *reinterpret_cast<const float4*>(
                    &Af[((mt * 4 + ks) * 32 + lane) * 4]);
                af[mi][0] = __float_as_uint(a.x);
                af[mi][1] = __float_as_uint(a.y);
                af[mi][2] = __float_as_uint(a.z);
                af[mi][3] = __float_as_uint(a.w);
            }
            #pragma unroll
            for (int ni = 0; ni < 4; ++ni) {
                int cB = wn * 32 + ni * 8 + g;
                uint32_t b0 = __float_as_uint(Bs[st][k8 + t][cB]);
                uint32_t b1 = __float_as_uint(Bs[st][k8 + t + 4][cB]);
                #pragma unroll
                for (int mi = 0; mi < 2; ++mi) {
                    asm volatile(
                        "mma.sync.aligned.m16n8k8.row.col.f32.tf32.tf32.f32 "
                        "{%0,%1,%2,%3}, {%4,%5,%6,%7}, {%8,%9}, {%0,%1,%2,%3};"
                        : "+f"(acc[mi][ni][0]), "+f"(acc[mi][ni][1]),
                          "+f"(acc[mi][ni][2]), "+f"(acc[mi][ni][3])
                        : "r"(af[mi][0]), "r"(af[mi][1]),
                          "r"(af[mi][2]), "r"(af[mi][3]),
                          "r"(b0), "r"(b1));
                }
            }
        }
        __syncthreads();
        if (cc + 1 < chunks) {
            if (CVTA) {
                areg0.x = f2tf_f(areg0.x); areg0.y = f2tf_f(areg0.y);
                areg0.z = f2tf_f(areg0.z); areg0.w = f2tf_f(areg0.w);
                areg1.x = f2tf_f(areg1.x); areg1.y = f2tf_f(areg1.y);
                areg1.z = f2tf_f(areg1.z); areg1.w = f2tf_f(areg1.w);
            }
            Af[base1 + 0]  = areg0.x; Af[base1 + 4]  = areg0.y;
            Af[base1 + 8]  = areg0.z; Af[base1 + 12] = areg0.w;
            Af[base2 + 0]  = areg1.x; Af[base2 + 4]  = areg1.y;
            Af[base2 + 8]  = areg1.z; Af[base2 + 12] = areg1.w;
        }
    }

    #pragma unroll
    for (int mi = 0; mi < 2; ++mi) {
        int r0 = m0 + wm * 32 + mi * 16 + g;
        #pragma unroll
        for (int ni = 0; ni < 4; ++ni) {
            int col = n0 + wn * 32 + ni * 8 + 2 * t;
            if (col >= N) continue;
            if (MODE == 0) {
                atomicAdd(&C[(size_t)r0 * ldc + col],           acc[mi][ni][0]);
                atomicAdd(&C[(size_t)r0 * ldc + col + 1],       acc[mi][ni][1]);
                atomicAdd(&C[(size_t)(r0 + 8) * ldc + col],     acc[mi][ni][2]);
                atomicAdd(&C[(size_t)(r0 + 8) * ldc + col + 1], acc[mi][ni][3]);
            } else if (MODE == 1) {
                float bv0 = bias[col], bv1 = bias[col + 1];
                float2 v0 = make_float2(acc[mi][ni][0] + bv0, acc[mi][ni][1] + bv1);
                float2 v1 = make_float2(acc[mi][ni][2] + bv0, acc[mi][ni][3] + bv1);
                *reinterpret_cast<float2*>(&C[(size_t)r0 * ldc + col]) = v0;
                *reinterpret_cast<float2*>(&C[(size_t)(r0 + 8) * ldc + col]) = v1;
            } else {
                if (col < Ncut) {
                    float bv0 = bias[col], bv1 = bias[col + 1];
                    float2 v0 = make_float2(acc[mi][ni][0] + bv0, acc[mi][ni][1] + bv1);
                    float2 v1 = make_float2(acc[mi][ni][2] + bv0, acc[mi][ni][3] + bv1);
                    *reinterpret_cast<float2*>(&C[(size_t)r0 * ldc + col]) = v0;
                    *reinterpret_cast<float2*>(&C[(size_t)(r0 + 8) * ldc + col]) = v1;
                } else {
                    int c2 = col - Ncut;
                    float bv0 = bias2[c2], bv1 = bias2[c2 + 1];
                    float2 v0 = make_float2(acc[mi][ni][0] + bv0, acc[mi][ni][1] + bv1);
                    float2 v1 = make_float2(acc[mi][ni][2] + bv0, acc[mi][ni][3] + bv1);
                    *reinterpret_cast<float2*>(&C2[(size_t)r0 * ldc2 + c2]) = v0;
                    *reinterpret_cast<float2*>(&C2[(size_t)(r0 + 8) * ldc2 + c2]) = v1;
                }
            }
        }
    }
}

// ---------------- fused scores + softmax + context + glue ----------------
// one block per batch element, 512 threads (16 warps)
__global__ void __launch_bounds__(512)
scores_ctx_kernel(const float* __restrict__ uhs,
                  const float* __restrict__ wah,
                  const float* __restrict__ Aw,
                  const float* __restrict__ Ab,
                  const int* __restrict__ captions,
                  const float* __restrict__ emb,
                  const float* __restrict__ bcat,
                  const float* __restrict__ hr,
                  const float* __restrict__ features,
                  float* __restrict__ incat,
                  float* __restrict__ gates,
                  float* __restrict__ alpha_out,
                  int t) {
    const int b = blockIdx.x;
    const int tid = threadIdx.x;
    const int warp = tid >> 5;
    const int lane = tid & 31;

    __shared__ __align__(16) float s_wah[ATT];
    __shared__ __align__(16) float s_Aw[ATT];
    __shared__ float s_sc[NF];
    __shared__ float s_al[NF];
    __shared__ float s_red[16];

    for (int i = tid; i < ATT; i += 512) {
        s_wah[i] = wah[b * ATT + i];
        s_Aw[i]  = Aw[i];
    }
    __syncthreads();

    // glue
    {
        int tok = captions[b * (TSTEPS + 1) + t];
        if (tid < EMB)
            incat[(size_t)b * KCAT + tid] = f2tf_f(emb[(size_t)tok * EMB + tid]);
        if (tid < DEC)
            incat[(size_t)b * KCAT + EMB + ENC + tid] = hr[b * DEC + tid];
        #pragma unroll
        for (int i = tid; i < GATES4; i += 512)
            gates[(size_t)b * GATES4 + i] = bcat[i];
    }

    const float Ab0 = Ab[0];
    // scores: hardware tanh, float4 loads, 4 accumulator chains
    for (int f = warp; f < NF; f += 16) {
        const float* u = uhs + ((size_t)(b * NF + f)) * ATT;
        float a0 = 0.f, a1 = 0.f, a2 = 0.f, a3 = 0.f;
        #pragma unroll
        for (int kk = 0; kk < 4; ++kk) {
            int k = kk * 128 + lane * 4;
            float4 uv = *reinterpret_cast<const float4*>(u + k);
            float4 wv = *reinterpret_cast<const float4*>(&s_wah[k]);
            float4 av = *reinterpret_cast<const float4*>(&s_Aw[k]);
            a0 += htanh(uv.x + wv.x) * av.x;
            a1 += htanh(uv.y + wv.y) * av.y;
            a2 += htanh(uv.z + wv.z) * av.z;
            a3 += htanh(uv.w + wv.w) * av.w;
        }
        float acc = (a0 + a1) + (a2 + a3);
        #pragma unroll
        for (int o = 16; o; o >>= 1) acc += __shfl_xor_sync(0xffffffffu, acc, o);
        if (lane == 0) s_sc[f] = acc + Ab0;
    }
    __syncthreads();

    // softmax over NF=196 (16 warps)
    float v = (tid < NF) ? s_sc[tid] : -1e30f;
    float m = v;
    #pragma unroll
    for (int o = 16; o; o >>= 1) m = fmaxf(m, __shfl_xor_sync(0xffffffffu, m, o));
    if (lane == 0) s_red[warp] = m;
    __syncthreads();
    if (tid == 0) {
        float mm = s_red[0];
        #pragma unroll
        for (int w = 1; w < 16; ++w) mm = fmaxf(mm, s_red[w]);
        s_red[0] = mm;
    }
    __syncthreads();
    const float mx = s_red[0];
    __syncthreads();
    float e = (tid < NF) ? expf(v - mx) : 0.f;
    float s = e;
    #pragma unroll
    for (int o = 16; o; o >>= 1) s += __shfl_xor_sync(0xffffffffu, s, o);
    if (lane == 0) s_red[warp] = s;
    __syncthreads();
    if (tid == 0) {
        float ss = 0.f;
        #pragma unroll
        for (int w = 0; w < 16; ++w) ss += s_red[w];
        s_red[0] = ss;
    }
    __syncthreads();
    const float inv_denom = 1.0f / s_red[0];
    if (tid < NF) {
        float alpha = e * inv_denom;
        s_al[tid] = alpha;
        alpha_out[(size_t)b * (TSTEPS * NF) + tid] = alpha;
    }
    __syncthreads();

    // context: each thread one float4 column group (512*4 = 2048 = ENC)
    {
        const int e4 = tid * 4;
        const float* fp = features + (size_t)b * NF * ENC + e4;
        float c0 = 0.f, c1 = 0.f, c2 = 0.f, c3 = 0.f;
        #pragma unroll 4
        for (int f = 0; f < NF; ++f) {
            float4 fv = *reinterpret_cast<const float4*>(fp + (size_t)f * ENC);
            float a = s_al[f];
            c0 += a * fv.x; c1 += a * fv.y; c2 += a * fv.z; c3 += a * fv.w;
        }
        float4 o4 = make_float4(f2tf_f(c0), f2tf_f(c1), f2tf_f(c2), f2tf_f(c3));
        *reinterpret_cast<float4*>(&incat[(size_t)b * KCAT + EMB + e4]) = o4;
    }
}

// ---------------- LSTM pointwise ----------------
__global__ void lstm_kernel(const float* __restrict__ gates,
                            float* __restrict__ hr,
                            float* __restrict__ c) {
    int idx = blockIdx.x * blockDim.x + threadIdx.x;
    if (idx >= B * DEC) return;
    int b = idx / DEC;
    int n = idx - b * DEC;
    const float* g = gates + (size_t)b * GATES4;
    float i_ = g[n];
    float f_ = g[DEC + n];
    float gg = g[2 * DEC + n];
    float o_ = g[3 * DEC + n];
    float cc = c[idx];
    cc = sigmoidf_(f_) * cc + sigmoidf_(i_) * tanhf(gg);
    c[idx] = cc;
    hr[idx] = f2tf_f(sigmoidf_(o_) * tanhf(cc));
}

// ---------------- launch ----------------
extern "C" void kernel_launch(void* const* d_in, const int* in_sizes, int n_in,
                              void* d_out, int out_size) {
    const float* features = (const float*)d_in[0];
    const int*   captions = (const int*)  d_in[1];
    const float* emb      = (const float*)d_in[2];
    const float* Uw       = (const float*)d_in[3];
    const float* Ub       = (const float*)d_in[4];
    const float* Ww       = (const float*)d_in[5];
    const float* Wb       = (const float*)d_in[6];
    const float* Aw       = (const float*)d_in[7];
    const float* Ab       = (const float*)d_in[8];
    const float* ih_w     = (const float*)d_in[9];
    const float* ih_b     = (const float*)d_in[10];
    const float* ic_w     = (const float*)d_in[11];
    const float* ic_b     = (const float*)d_in[12];
    const float* W_ih     = (const float*)d_in[13];
    const float* b_ih     = (const float*)d_in[14];
    const float* W_hh     = (const float*)d_in[15];
    const float* b_hh     = (const float*)d_in[16];
    const float* fcn_w    = (const float*)d_in[17];
    const float* fcn_b    = (const float*)d_in[18];
    float* out = (float*)d_out;

    float* S = nullptr;
    cudaGetSymbolAddress((void**)&S, g_scratch);
    float* uhs   = S + OFF_UHS;
    float* Wcat  = S + OFF_WCAT;
    float* W2    = S + OFF_W2;
    float* ihr   = S + OFF_IHR;
    float* icr   = S + OFF_ICR;
    float* uwr   = S + OFF_UWR;
    float* meanf = S + OFF_MEANF;
    float* h     = S + OFF_H;
    float* c     = S + OFF_C;
    float* hr    = S + OFF_HR;
    float* wah   = S + OFF_WAH;
    float* incat = S + OFF_INCAT;
    float* gates = S + OFF_GATES;
    float* bcat  = S + OFF_BCAT;

    // ---- prep (uhs GEMM is launch #6 -> profiled by ncu -s 5 -c 1) ----
    prep_wcat_kernel<<<2048, 256>>>(W_ih, W_hh, b_ih, b_hh, Wcat, bcat);   // 1
    prep_w2_kernel<<<2048, 256>>>(fcn_w, Ww, W2);                          // 2
    round_copy_kernel<<<512, 256>>>(Uw, uwr, ENC * ATT);                   // 3
    round_copy_kernel<<<512, 256>>>(ih_w, ihr, ENC * DEC);                 // 4
    round_copy_kernel<<<512, 256>>>(ic_w, icr, ENC * DEC);                 // 5
    // u_hs = round(features) @ uwr + Ub  (12544 x 512 x 2048)             // 6
    tf32_gemm<1, true><<<dim3(ATT / 128, (B * NF) / 64, 1), 256>>>(
        features, ENC, uwr, ATT, uhs, ATT, Ub, nullptr, 0, nullptr,
        B * NF, ATT, ENC, 0);
    meanf_kernel<<<(B * ENC + 255) / 256, 256>>>(features, meanf);         // 7
    // h0, c0 (64 x 512 x 2048, single-z, bias epilogue)
    tf32_gemm<1, false><<<dim3(DEC / 128, 1, 1), 256>>>(meanf, ENC, ihr, DEC,
        h, DEC, ih_b, nullptr, 0, nullptr, B, DEC, ENC, 0);                // 8
    tf32_gemm<1, false><<<dim3(DEC / 128, 1, 1), 256>>>(meanf, ENC, icr, DEC,
        c, DEC, ic_b, nullptr, 0, nullptr, B, DEC, ENC, 0);                // 9
    round_copy_kernel<<<(B * DEC + 255) / 256, 256>>>(h, hr, B * DEC);     // 10
    // wah0 = hr @ Ww + Wb (Ww slice of W2)
    tf32_gemm<1, false><<<dim3(ATT / 128, 1, 1), 256>>>(hr, DEC, W2 + VOC, N2,
        wah, ATT, Wb, nullptr, 0, nullptr, B, ATT, DEC, 0);                // 11

    // ---- recurrent steps (4 launches/step) ----
    for (int t = 0; t < TSTEPS; ++t) {
        float* alpha_t = out + ALPHA_OFF + (size_t)t * NF;
        scores_ctx_kernel<<<B, 512>>>(uhs, wah, Aw, Ab, captions, emb, bcat,
                                      hr, features, incat, gates, alpha_t, t);
        tf32_gemm<0, false><<<dim3(GATES4 / 128, 1, 8), 256>>>(incat, KCAT,
            Wcat, GATES4, gates, GATES4, nullptr, nullptr, 0, nullptr,
            B, GATES4, KCAT, 0);
        lstm_kernel<<<(B * DEC + 255) / 256, 256>>>(gates, hr, c);
        tf32_gemm<2, false><<<dim3((N2 + 127) / 128, 1, 1), 256>>>(hr, DEC,
            W2, N2, out + (size_t)t * VOC, TSTEPS * VOC, fcn_b,
            wah, ATT, Wb, B, N2, DEC, VOC);
    }
}

// round 6
// speedup vs baseline: 5.4597x; 1.3821x over previous
#include <cuda_runtime.h>
#include <math.h>
#include <stdint.h>

// ---------------- problem constants ----------------
#define B    64
#define NF   196
#define ENC  2048
#define DEC  512
#define ATT  512
#define VOC  30000
#define EMB  512
#define TSTEPS 24
#define KCAT (EMB + ENC + DEC)   // 3072
#define GATES4 (4*DEC)           // 2048
#define N2   (VOC + ATT)         // 30512

#define ALPHA_OFF ((size_t)B * TSTEPS * VOC)

// ---------------- scratch ----------------
#define OFF_UHS    ((size_t)0)
#define OFF_WCAT   (OFF_UHS   + (size_t)B*NF*ATT)
#define OFF_W2     (OFF_WCAT  + (size_t)KCAT*GATES4)
#define OFF_IHR    (OFF_W2    + (size_t)DEC*N2)
#define OFF_ICR    (OFF_IHR   + (size_t)ENC*DEC)
#define OFF_UWR    (OFF_ICR   + (size_t)ENC*DEC)
#define OFF_MEANF  (OFF_UWR   + (size_t)ENC*ATT)
#define OFF_H      (OFF_MEANF + (size_t)B*ENC)
#define OFF_C      (OFF_H     + (size_t)B*DEC)
#define OFF_HR0    (OFF_C     + (size_t)B*DEC)
#define OFF_HR1    (OFF_HR0   + (size_t)B*DEC)
#define OFF_WAH    (OFF_HR1   + (size_t)B*DEC)
#define OFF_INCAT  (OFF_WAH   + (size_t)B*ATT)
#define OFF_GATES  (OFF_INCAT + (size_t)B*KCAT)
#define OFF_BCAT   (OFF_GATES + (size_t)B*GATES4)
#define OFF_SC     (OFF_BCAT  + (size_t)GATES4)
#define SCRATCH_TOTAL (OFF_SC + (size_t)B*NF)

__device__ __align__(16) float g_scratch[SCRATCH_TOTAL];

__device__ __forceinline__ float sigmoidf_(float x) {
    return 1.0f / (1.0f + expf(-x));
}
__device__ __forceinline__ float f2tf_f(float x) {
    uint32_t r;
    asm("cvt.rna.tf32.f32 %0, %1;" : "=r"(r) : "f"(x));
    return __uint_as_float(r);
}
__device__ __forceinline__ float htanh(float x) {
    float y;
    asm("tanh.approx.f32 %0, %1;" : "=f"(y) : "f"(x));
    return y;
}

// ---------------- prep kernels ----------------
__global__ void prep_wcat_kernel(const float* __restrict__ W_ih,
                                 const float* __restrict__ W_hh,
                                 const float* __restrict__ b_ih,
                                 const float* __restrict__ b_hh,
                                 float* __restrict__ Wcat,
                                 float* __restrict__ bcat) {
    int total = KCAT * GATES4;
    for (int i = blockIdx.x * blockDim.x + threadIdx.x; i < total;
         i += gridDim.x * blockDim.x) {
        int r = i / GATES4;
        int c = i - r * GATES4;
        float v = (r < EMB + ENC) ? W_ih[i] : W_hh[(r - (EMB + ENC)) * GATES4 + c];
        Wcat[i] = f2tf_f(v);
    }
    int idx = blockIdx.x * blockDim.x + threadIdx.x;
    if (idx < GATES4) bcat[idx] = b_ih[idx] + b_hh[idx];
}

__global__ void prep_w2_kernel(const float* __restrict__ fcn_w,
                               const float* __restrict__ Ww,
                               float* __restrict__ W2) {
    int total = DEC * N2;
    for (int i = blockIdx.x * blockDim.x + threadIdx.x; i < total;
         i += gridDim.x * blockDim.x) {
        int k = i / N2;
        int c = i - k * N2;
        float v = (c < VOC) ? fcn_w[(size_t)k * VOC + c]
                            : Ww[(size_t)k * ATT + (c - VOC)];
        W2[i] = f2tf_f(v);
    }
}

__global__ void round_copy_kernel(const float* __restrict__ src,
                                  float* __restrict__ dst, int n) {
    for (int i = blockIdx.x * blockDim.x + threadIdx.x; i < n;
         i += gridDim.x * blockDim.x)
        dst[i] = f2tf_f(src[i]);
}

__global__ void meanf_kernel(const float* __restrict__ features,
                             float* __restrict__ meanf) {
    int idx = blockIdx.x * blockDim.x + threadIdx.x;
    if (idx < B * ENC) {
        int b = idx >> 11;
        int e = idx & (ENC - 1);
        const float* p = features + (size_t)b * NF * ENC + e;
        float s0 = 0.f, s1 = 0.f, s2 = 0.f, s3 = 0.f;
        int f = 0;
        #pragma unroll 1
        for (; f + 4 <= NF; f += 4) {
            s0 += p[(size_t)(f + 0) * ENC];
            s1 += p[(size_t)(f + 1) * ENC];
            s2 += p[(size_t)(f + 2) * ENC];
            s3 += p[(size_t)(f + 3) * ENC];
        }
        for (; f < NF; ++f) s0 += p[(size_t)f * ENC];
        meanf[idx] = f2tf_f(((s0 + s1) + (s2 + s3)) * (1.0f / (float)NF));
    }
}

// ---------------- tf32 tensor-core GEMM ----------------
// C(M,N) = A(M,K) @ B(K,N). B pre-rounded tf32; A pre-rounded unless CVTA.
// block 64x128, 8 warps, warp 32x32, mma.m16n8k8, cp.async double-buffered B.
// MODE 0: atomicAdd into pre-initialized C (K-split via gridDim.z)
// MODE 1: C = acc + bias
template <int MODE, bool CVTA>
__global__ void __launch_bounds__(256)
tf32_gemm(const float* __restrict__ A, int lda,
          const float* __restrict__ Bm, int ldb,
          float* __restrict__ C, int ldc,
          const float* __restrict__ bias,
          int M, int N, int K) {
    __shared__ __align__(16) float Af[2048];
    __shared__ __align__(16) float Bs[2][32][136];

    const int tid  = threadIdx.x;
    const int lane = tid & 31;
    const int warp = tid >> 5;
    const int wm = warp >> 2;
    const int wn = warp & 3;
    const int g = lane >> 2;
    const int t = lane & 3;

    const int m0 = blockIdx.y * 64;
    const int n0 = blockIdx.x * 128;
    const int chunks = (K / 32) / gridDim.z;
    const int kc0 = blockIdx.z * chunks;

    const int arow = tid >> 3;
    const int ac4  = (tid & 7) * 4;

    const int ksA = ac4 >> 3;
    const int eA  = (ac4 & 4) ? 2 : 0;
    const int r1 = arow, r2 = arow + 32;
    const int mt1 = r1 >> 4, mt2 = r2 >> 4;
    const int g1 = r1 & 7;
    const int e1 = eA + ((r1 >> 3) & 1);
    const int e2 = eA + ((r2 >> 3) & 1);
    const int base1 = ((mt1 * 4 + ksA) * 32 + g1 * 4) * 4 + e1;
    const int base2 = ((mt2 * 4 + ksA) * 32 + g1 * 4) * 4 + e2;

    float acc[2][4][4];
    #pragma unroll
    for (int mi = 0; mi < 2; ++mi)
        #pragma unroll
        for (int ni = 0; ni < 4; ++ni)
            #pragma unroll
            for (int q = 0; q < 4; ++q) acc[mi][ni][q] = 0.f;

    float4 areg0, areg1;

    {
        const int k0 = kc0 * 32;
        areg0 = *reinterpret_cast<const float4*>(A + (size_t)(m0 + r1) * lda + k0 + ac4);
        areg1 = *reinterpret_cast<const float4*>(A + (size_t)(m0 + r2) * lda + k0 + ac4);
        #pragma unroll
        for (int i = 0; i < 4; ++i) {
            int j = tid + i * 256;
            int r = j >> 5;
            int c4 = (j & 31) * 4;
            int col = n0 + c4;
            const float* src = Bm + (size_t)(k0 + r) * ldb + (col < N ? col : 0);
            uint32_t saddr = (uint32_t)__cvta_generic_to_shared(&Bs[0][r][c4]);
            int sz = (col < N) ? 16 : 0;
            asm volatile("cp.async.cg.shared.global [%0], [%1], 16, %2;\n"
                         :: "r"(saddr), "l"(src), "r"(sz));
        }
        asm volatile("cp.async.commit_group;\n");
        if (CVTA) {
            areg0.x = f2tf_f(areg0.x); areg0.y = f2tf_f(areg0.y);
            areg0.z = f2tf_f(areg0.z); areg0.w = f2tf_f(areg0.w);
            areg1.x = f2tf_f(areg1.x); areg1.y = f2tf_f(areg1.y);
            areg1.z = f2tf_f(areg1.z); areg1.w = f2tf_f(areg1.w);
        }
        Af[base1 + 0]  = areg0.x; Af[base1 + 4]  = areg0.y;
        Af[base1 + 8]  = areg0.z; Af[base1 + 12] = areg0.w;
        Af[base2 + 0]  = areg1.x; Af[base2 + 4]  = areg1.y;
        Af[base2 + 8]  = areg1.z; Af[base2 + 12] = areg1.w;
    }

    for (int cc = 0; cc < chunks; ++cc) {
        const int st = cc & 1;
        if (cc + 1 < chunks) {
            const int k0 = (kc0 + cc + 1) * 32;
            #pragma unroll
            for (int i = 0; i < 4; ++i) {
                int j = tid + i * 256;
                int r = j >> 5;
                int c4 = (j & 31) * 4;
                int col = n0 + c4;
                const float* src = Bm + (size_t)(k0 + r) * ldb + (col < N ? col : 0);
                uint32_t saddr = (uint32_t)__cvta_generic_to_shared(&Bs[st ^ 1][r][c4]);
                int sz = (col < N) ? 16 : 0;
                asm volatile("cp.async.cg.shared.global [%0], [%1], 16, %2;\n"
                             :: "r"(saddr), "l"(src), "r"(sz));
            }
            areg0 = *reinterpret_cast<const float4*>(A + (size_t)(m0 + r1) * lda + k0 + ac4);
            areg1 = *reinterpret_cast<const float4*>(A + (size_t)(m0 + r2) * lda + k0 + ac4);
        }
        asm volatile("cp.async.commit_group;\n");
        asm volatile("cp.async.wait_group 1;\n");
        __syncthreads();

        #pragma unroll
        for (int ks = 0; ks < 4; ++ks) {
            const int k8 = ks * 8;
            uint32_t af[2][4];
            #pragma unroll
            for (int mi = 0; mi < 2; ++mi) {
                int mt = wm * 2 + mi;
                float4 a = *reinterpret_cast<const float4*>(
                    &Af[((mt * 4 + ks) * 32 + lane) * 4]);
                af[mi][0] = __float_as_uint(a.x);
                af[mi][1] = __float_as_uint(a.y);
                af[mi][2] = __float_as_uint(a.z);
                af[mi][3] = __float_as_uint(a.w);
            }
            #pragma unroll
            for (int ni = 0; ni < 4; ++ni) {
                int cB = wn * 32 + ni * 8 + g;
                uint32_t b0 = __float_as_uint(Bs[st][k8 + t][cB]);
                uint32_t b1 = __float_as_uint(Bs[st][k8 + t + 4][cB]);
                #pragma unroll
                for (int mi = 0; mi < 2; ++mi) {
                    asm volatile(
                        "mma.sync.aligned.m16n8k8.row.col.f32.tf32.tf32.f32 "
                        "{%0,%1,%2,%3}, {%4,%5,%6,%7}, {%8,%9}, {%0,%1,%2,%3};"
                        : "+f"(acc[mi][ni][0]), "+f"(acc[mi][ni][1]),
                          "+f"(acc[mi][ni][2]), "+f"(acc[mi][ni][3])
                        : "r"(af[mi][0]), "r"(af[mi][1]),
                          "r"(af[mi][2]), "r"(af[mi][3]),
                          "r"(b0), "r"(b1));
                }
            }
        }
        __syncthreads();
        if (cc + 1 < chunks) {
            if (CVTA) {
                areg0.x = f2tf_f(areg0.x); areg0.y = f2tf_f(areg0.y);
                areg0.z = f2tf_f(areg0.z); areg0.w = f2tf_f(areg0.w);
                areg1.x = f2tf_f(areg1.x); areg1.y = f2tf_f(areg1.y);
                areg1.z = f2tf_f(areg1.z); areg1.w = f2tf_f(areg1.w);
            }
            Af[base1 + 0]  = areg0.x; Af[base1 + 4]  = areg0.y;
            Af[base1 + 8]  = areg0.z; Af[base1 + 12] = areg0.w;
            Af[base2 + 0]  = areg1.x; Af[base2 + 4]  = areg1.y;
            Af[base2 + 8]  = areg1.z; Af[base2 + 12] = areg1.w;
        }
    }

    #pragma unroll
    for (int mi = 0; mi < 2; ++mi) {
        int r0 = m0 + wm * 32 + mi * 16 + g;
        #pragma unroll
        for (int ni = 0; ni < 4; ++ni) {
            int col = n0 + wn * 32 + ni * 8 + 2 * t;
            if (col >= N) continue;
            if (MODE == 0) {
                atomicAdd(&C[(size_t)r0 * ldc + col],           acc[mi][ni][0]);
                atomicAdd(&C[(size_t)r0 * ldc + col + 1],       acc[mi][ni][1]);
                atomicAdd(&C[(size_t)(r0 + 8) * ldc + col],     acc[mi][ni][2]);
                atomicAdd(&C[(size_t)(r0 + 8) * ldc + col + 1], acc[mi][ni][3]);
            } else {
                float bv0 = bias[col], bv1 = bias[col + 1];
                float2 v0 = make_float2(acc[mi][ni][0] + bv0, acc[mi][ni][1] + bv1);
                float2 v1 = make_float2(acc[mi][ni][2] + bv0, acc[mi][ni][3] + bv1);
                *reinterpret_cast<float2*>(&C[(size_t)r0 * ldc + col]) = v0;
                *reinterpret_cast<float2*>(&C[(size_t)(r0 + 8) * ldc + col]) = v1;
            }
        }
    }
}

// ---------------- scores: grid (4, B), 256 threads ----------------
__global__ void __launch_bounds__(256)
scores_kernel(const float* __restrict__ uhs,
              const float* __restrict__ wah,
              const float* __restrict__ Aw,
              const float* __restrict__ Ab,
              const int* __restrict__ captions,
              const float* __restrict__ emb,
              const float* __restrict__ bcat,
              const float* __restrict__ hr,
              float* __restrict__ incat,
              float* __restrict__ gates,
              float* __restrict__ scores,
              int t) {
    const int q = blockIdx.x;      // 0..3
    const int b = blockIdx.y;
    const int tid = threadIdx.x;
    const int warp = tid >> 5;
    const int lane = tid & 31;

    __shared__ __align__(16) float s_wah[ATT];
    __shared__ __align__(16) float s_Aw[ATT];

    for (int i = tid; i < ATT; i += 256) {
        s_wah[i] = wah[b * ATT + i];
        s_Aw[i]  = Aw[i];
    }
    __syncthreads();

    // glue, slice q
    {
        int tok = captions[b * (TSTEPS + 1) + t];
        if (tid < 128) {
            int iq = q * 128 + tid;
            incat[(size_t)b * KCAT + iq] = f2tf_f(emb[(size_t)tok * EMB + iq]);
            incat[(size_t)b * KCAT + EMB + ENC + iq] = hr[b * DEC + iq];
        }
        int i0 = q * 512 + tid;
        gates[(size_t)b * GATES4 + i0]       = bcat[i0];
        gates[(size_t)b * GATES4 + i0 + 256] = bcat[i0 + 256];
    }

    const float Ab0 = Ab[0];
    const int f0 = q * 49;
    for (int f = f0 + warp; f < f0 + 49; f += 8) {
        const float* u = uhs + ((size_t)(b * NF + f)) * ATT;
        float a0 = 0.f, a1 = 0.f, a2 = 0.f, a3 = 0.f;
        #pragma unroll
        for (int kk = 0; kk < 4; ++kk) {
            int k = kk * 128 + lane * 4;
            float4 uv = *reinterpret_cast<const float4*>(u + k);
            float4 wv = *reinterpret_cast<const float4*>(&s_wah[k]);
            float4 av = *reinterpret_cast<const float4*>(&s_Aw[k]);
            a0 += htanh(uv.x + wv.x) * av.x;
            a1 += htanh(uv.y + wv.y) * av.y;
            a2 += htanh(uv.z + wv.z) * av.z;
            a3 += htanh(uv.w + wv.w) * av.w;
        }
        float acc = (a0 + a1) + (a2 + a3);
        #pragma unroll
        for (int o = 16; o; o >>= 1) acc += __shfl_xor_sync(0xffffffffu, acc, o);
        if (lane == 0) scores[b * NF + f] = acc + Ab0;
    }
}

// ---------------- ctx: softmax (recomputed per block) + context slice ------
// grid (4, B), 512 threads
__global__ void __launch_bounds__(512)
ctx_kernel(const float* __restrict__ scores,
           const float* __restrict__ features,
           float* __restrict__ incat,
           float* __restrict__ alpha_out) {
    const int y = blockIdx.x;      // 0..3 column slice
    const int b = blockIdx.y;
    const int tid = threadIdx.x;
    const int warp = tid >> 5;
    const int lane = tid & 31;

    __shared__ float s_al[NF];
    __shared__ float s_red[16];
    __shared__ __align__(16) float4 s_part[4][128];

    // softmax over NF=196
    float v = (tid < NF) ? scores[b * NF + tid] : -1e30f;
    float m = v;
    #pragma unroll
    for (int o = 16; o; o >>= 1) m = fmaxf(m, __shfl_xor_sync(0xffffffffu, m, o));
    if (lane == 0) s_red[warp] = m;
    __syncthreads();
    if (tid == 0) {
        float mm = s_red[0];
        #pragma unroll
        for (int w = 1; w < 16; ++w) mm = fmaxf(mm, s_red[w]);
        s_red[0] = mm;
    }
    __syncthreads();
    const float mx = s_red[0];
    __syncthreads();
    float e = (tid < NF) ? expf(v - mx) : 0.f;
    float s = e;
    #pragma unroll
    for (int o = 16; o; o >>= 1) s += __shfl_xor_sync(0xffffffffu, s, o);
    if (lane == 0) s_red[warp] = s;
    __syncthreads();
    if (tid == 0) {
        float ss = 0.f;
        #pragma unroll
        for (int w = 0; w < 16; ++w) ss += s_red[w];
        s_red[0] = ss;
    }
    __syncthreads();
    const float inv_denom = 1.0f / s_red[0];
    if (tid < NF) {
        float alpha = e * inv_denom;
        s_al[tid] = alpha;
        if (y == 0)
            alpha_out[(size_t)b * (TSTEPS * NF) + tid] = alpha;
    }
    __syncthreads();

    // context slice: cols [y*512, y*512+512), 4 f-subgroups of 49
    const int sub = tid >> 7;        // 0..3
    const int c4  = tid & 127;       // 0..127
    const int col = y * 512 + c4 * 4;
    const float* fp = features + (size_t)b * NF * ENC + col;
    float cx = 0.f, cy = 0.f, cz = 0.f, cw = 0.f;
    const int fs = sub * 49;
    #pragma unroll 7
    for (int f = fs; f < fs + 49; ++f) {
        float4 fv = *reinterpret_cast<const float4*>(fp + (size_t)f * ENC);
        float a = s_al[f];
        cx += a * fv.x; cy += a * fv.y; cz += a * fv.z; cw += a * fv.w;
    }
    s_part[sub][c4] = make_float4(cx, cy, cz, cw);
    __syncthreads();
    if (tid < 128) {
        float4 p0 = s_part[0][tid], p1 = s_part[1][tid];
        float4 p2 = s_part[2][tid], p3 = s_part[3][tid];
        float4 r = make_float4(f2tf_f(p0.x + p1.x + p2.x + p3.x),
                               f2tf_f(p0.y + p1.y + p2.y + p3.y),
                               f2tf_f(p0.z + p1.z + p2.z + p3.z),
                               f2tf_f(p0.w + p1.w + p2.w + p3.w));
        *reinterpret_cast<float4*>(&incat[(size_t)b * KCAT + EMB + y * 512 + tid * 4]) = r;
    }
}

// ---------------- LSTM pointwise + wah bias-init ----------------
__global__ void lstm_kernel(const float* __restrict__ gates,
                            float* __restrict__ hr,
                            float* __restrict__ c,
                            float* __restrict__ wah,
                            const float* __restrict__ Wb) {
    int idx = blockIdx.x * blockDim.x + threadIdx.x;
    if (idx >= B * DEC) return;
    int b = idx / DEC;
    int n = idx - b * DEC;
    const float* g = gates + (size_t)b * GATES4;
    float i_ = g[n];
    float f_ = g[DEC + n];
    float gg = g[2 * DEC + n];
    float o_ = g[3 * DEC + n];
    float cc = c[idx];
    cc = sigmoidf_(f_) * cc + sigmoidf_(i_) * tanhf(gg);
    c[idx] = cc;
    hr[idx] = f2tf_f(sigmoidf_(o_) * tanhf(cc));
    wah[idx] = Wb[idx & (ATT - 1)];
}

// ---------------- launch ----------------
extern "C" void kernel_launch(void* const* d_in, const int* in_sizes, int n_in,
                              void* d_out, int out_size) {
    const float* features = (const float*)d_in[0];
    const int*   captions = (const int*)  d_in[1];
    const float* emb      = (const float*)d_in[2];
    const float* Uw       = (const float*)d_in[3];
    const float* Ub       = (const float*)d_in[4];
    const float* Ww       = (const float*)d_in[5];
    const float* Wb       = (const float*)d_in[6];
    const float* Aw       = (const float*)d_in[7];
    const float* Ab       = (const float*)d_in[8];
    const float* ih_w     = (const float*)d_in[9];
    const float* ih_b     = (const float*)d_in[10];
    const float* ic_w     = (const float*)d_in[11];
    const float* ic_b     = (const float*)d_in[12];
    const float* W_ih     = (const float*)d_in[13];
    const float* b_ih     = (const float*)d_in[14];
    const float* W_hh     = (const float*)d_in[15];
    const float* b_hh     = (const float*)d_in[16];
    const float* fcn_w    = (const float*)d_in[17];
    const float* fcn_b    = (const float*)d_in[18];
    float* out = (float*)d_out;

    float* S = nullptr;
    cudaGetSymbolAddress((void**)&S, g_scratch);
    float* uhs   = S + OFF_UHS;
    float* Wcat  = S + OFF_WCAT;
    float* W2    = S + OFF_W2;
    float* ihr   = S + OFF_IHR;
    float* icr   = S + OFF_ICR;
    float* uwr   = S + OFF_UWR;
    float* meanf = S + OFF_MEANF;
    float* h     = S + OFF_H;
    float* c     = S + OFF_C;
    float* hrb[2] = { S + OFF_HR0, S + OFF_HR1 };
    float* wah   = S + OFF_WAH;
    float* incat = S + OFF_INCAT;
    float* gates = S + OFF_GATES;
    float* bcat  = S + OFF_BCAT;
    float* sc    = S + OFF_SC;

    // second stream + events for off-critical-path preds GEMM
    cudaStream_t s2;
    cudaStreamCreateWithFlags(&s2, cudaStreamNonBlocking);
    cudaEvent_t fork_ev[2], join_ev[2];
    for (int i = 0; i < 2; ++i) {
        cudaEventCreateWithFlags(&fork_ev[i], cudaEventDisableTiming);
        cudaEventCreateWithFlags(&join_ev[i], cudaEventDisableTiming);
    }

    // ---- prep (uhs GEMM is 5th launch -> ncu -s 5 profiles it) ----
    prep_wcat_kernel<<<2048, 256>>>(W_ih, W_hh, b_ih, b_hh, Wcat, bcat);   // 1
    prep_w2_kernel<<<2048, 256>>>(fcn_w, Ww, W2);                          // 2
    round_copy_kernel<<<512, 256>>>(Uw, uwr, ENC * ATT);                   // 3
    meanf_kernel<<<(B * ENC + 255) / 256, 256>>>(features, meanf);         // 4
    tf32_gemm<1, true><<<dim3(ATT / 128, (B * NF) / 64, 1), 256>>>(        // 5
        features, ENC, uwr, ATT, uhs, ATT, Ub, B * NF, ATT, ENC);
    round_copy_kernel<<<512, 256>>>(ih_w, ihr, ENC * DEC);                 // 6
    round_copy_kernel<<<512, 256>>>(ic_w, icr, ENC * DEC);                 // 7
    tf32_gemm<1, false><<<dim3(DEC / 128, 1, 1), 256>>>(meanf, ENC, ihr, DEC,
        h, DEC, ih_b, B, DEC, ENC);                                        // 8
    tf32_gemm<1, false><<<dim3(DEC / 128, 1, 1), 256>>>(meanf, ENC, icr, DEC,
        c, DEC, ic_b, B, DEC, ENC);                                        // 9
    round_copy_kernel<<<(B * DEC + 255) / 256, 256>>>(h, hrb[1], B * DEC); // 10
    tf32_gemm<1, false><<<dim3(ATT / 128, 1, 1), 256>>>(hrb[1], DEC,
        W2 + VOC, N2, wah, ATT, Wb, B, ATT, DEC);                          // 11

    // ---- recurrent steps ----
    for (int t = 0; t < TSTEPS; ++t) {
        float* alpha_t = out + ALPHA_OFF + (size_t)t * NF;
        float* hr_in  = hrb[(t + 1) & 1];   // h_{t}
        float* hr_out = hrb[t & 1];         // h_{t+1}

        scores_kernel<<<dim3(4, B), 256>>>(uhs, wah, Aw, Ab, captions, emb,
                                           bcat, hr_in, incat, gates, sc, t);
        ctx_kernel<<<dim3(4, B), 512>>>(sc, features, incat, alpha_t);
        tf32_gemm<0, false><<<dim3(GATES4 / 128, 1, 8), 256>>>(incat, KCAT,
            Wcat, GATES4, gates, GATES4, nullptr, B, GATES4, KCAT);
        // preds GEMM from 2 steps ago must be done reading hr_out's buffer
        if (t >= 2) cudaStreamWaitEvent(0, join_ev[t & 1], 0);
        lstm_kernel<<<(B * DEC + 255) / 256, 256>>>(gates, hr_out, c, wah, Wb);
        cudaEventRecord(fork_ev[t & 1], 0);
        // wah_{t+1} = h_{t+1} @ Ww + Wb (critical path, small)
        tf32_gemm<0, false><<<dim3(ATT / 128, 1, 4), 256>>>(hr_out, DEC,
            W2 + VOC, N2, wah, ATT, nullptr, B, ATT, DEC);
        // preds_t = h_{t+1} @ fcn_w + fcn_b  — off critical path, stream s2
        cudaStreamWaitEvent(s2, fork_ev[t & 1], 0);
        tf32_gemm<1, false><<<dim3((VOC + 127) / 128, 1, 1), 256, 0, s2>>>(
            hr_out, DEC, W2, N2, out + (size_t)t * VOC, TSTEPS * VOC, fcn_b,
            B, VOC, DEC);
        cudaEventRecord(join_ev[t & 1], s2);
    }
    // rejoin forked stream before capture ends
    cudaStreamWaitEvent(0, join_ev[(TSTEPS - 1) & 1], 0);
    cudaStreamWaitEvent(0, join_ev[(TSTEPS - 2) & 1], 0);
}

// round 7
// speedup vs baseline: 8.3768x; 1.5343x over previous
#include <cuda_runtime.h>
#include <cuda_fp16.h>
#include <math.h>
#include <stdint.h>

// ---------------- problem constants ----------------
#define B    64
#define NF   196
#define ENC  2048
#define DEC  512
#define ATT  512
#define VOC  30000
#define EMB  512
#define TSTEPS 24
#define KCAT (EMB + ENC + DEC)   // 3072
#define GATES4 (4*DEC)           // 2048
#define N2   (VOC + ATT)         // 30512

#define ALPHA_OFF ((size_t)B * TSTEPS * VOC)

// ---------------- scratch (float-sized slots; halves/u32 carved out) -------
#define OFF_UHSH   ((size_t)0)                                  // B*NF*ATT/2
#define OFF_WCATP  (OFF_UHSH  + (size_t)B*NF*ATT/2)             // (KCAT/2)*GATES4
#define OFF_W2P    (OFF_WCATP + (size_t)(KCAT/2)*GATES4)        // (DEC/2)*N2
#define OFF_IHP    (OFF_W2P   + (size_t)(DEC/2)*N2)
#define OFF_ICP    (OFF_IHP   + (size_t)(ENC/2)*DEC)
#define OFF_UWP    (OFF_ICP   + (size_t)(ENC/2)*DEC)
#define OFF_FEATH  (OFF_UWP   + (size_t)(ENC/2)*ATT)            // B*NF*ENC/2
#define OFF_MEANFH (OFF_FEATH + (size_t)B*NF*ENC/2)             // B*ENC/2
#define OFF_C      (OFF_MEANFH+ (size_t)B*ENC/2)                // fp32
#define OFF_HRH0   (OFF_C     + (size_t)B*DEC)                  // B*DEC/2
#define OFF_HRH1   (OFF_HRH0  + (size_t)B*DEC/2)
#define OFF_WAH    (OFF_HRH1  + (size_t)B*DEC/2)                // fp32
#define OFF_INCATH (OFF_WAH   + (size_t)B*ATT)                  // B*KCAT/2
#define OFF_GATES  (OFF_INCATH+ (size_t)B*KCAT/2)               // fp32
#define OFF_BCAT   (OFF_GATES + (size_t)B*GATES4)
#define OFF_SC     (OFF_BCAT  + (size_t)GATES4)
#define SCRATCH_TOTAL (OFF_SC + (size_t)B*NF)

__device__ __align__(16) float g_scratch[SCRATCH_TOTAL];

__device__ __forceinline__ float sigmoidf_(float x) {
    return 1.0f / (1.0f + expf(-x));
}
__device__ __forceinline__ float htanh(float x) {
    float y;
    asm("tanh.approx.f32 %0, %1;" : "=f"(y) : "f"(x));
    return y;
}
__device__ __forceinline__ uint32_t h2u(__half2 v) {
    return *reinterpret_cast<uint32_t*>(&v);
}

// ---------------- prep: pack weights into k-pair half2 layout ----------------
// P[kp*N + n] = half2(W[2kp][n], W[2kp+1][n])
__global__ void pack_weight_kernel(const float* __restrict__ W,
                                   uint32_t* __restrict__ P, int K, int N) {
    int total = (K / 2) * N;
    for (int i = blockIdx.x * blockDim.x + threadIdx.x; i < total;
         i += gridDim.x * blockDim.x) {
        int kp = i / N;
        int n = i - kp * N;
        __half2 v = __floats2half2_rn(W[(size_t)(2 * kp) * N + n],
                                      W[(size_t)(2 * kp + 1) * N + n]);
        P[i] = h2u(v);
    }
}

__global__ void prep_wcat_kernel(const float* __restrict__ W_ih,
                                 const float* __restrict__ W_hh,
                                 const float* __restrict__ b_ih,
                                 const float* __restrict__ b_hh,
                                 uint32_t* __restrict__ WcatP,
                                 float* __restrict__ bcat) {
    int total = (KCAT / 2) * GATES4;
    for (int i = blockIdx.x * blockDim.x + threadIdx.x; i < total;
         i += gridDim.x * blockDim.x) {
        int kp = i / GATES4;
        int n = i - kp * GATES4;
        int r0 = 2 * kp, r1 = 2 * kp + 1;
        float v0 = (r0 < EMB + ENC) ? W_ih[(size_t)r0 * GATES4 + n]
                                    : W_hh[(size_t)(r0 - EMB - ENC) * GATES4 + n];
        float v1 = (r1 < EMB + ENC) ? W_ih[(size_t)r1 * GATES4 + n]
                                    : W_hh[(size_t)(r1 - EMB - ENC) * GATES4 + n];
        WcatP[i] = h2u(__floats2half2_rn(v0, v1));
    }
    int idx = blockIdx.x * blockDim.x + threadIdx.x;
    if (idx < GATES4) bcat[idx] = b_ih[idx] + b_hh[idx];
}

__global__ void prep_w2_kernel(const float* __restrict__ fcn_w,
                               const float* __restrict__ Ww,
                               uint32_t* __restrict__ W2P) {
    int total = (DEC / 2) * N2;
    for (int i = blockIdx.x * blockDim.x + threadIdx.x; i < total;
         i += gridDim.x * blockDim.x) {
        int kp = i / N2;
        int c = i - kp * N2;
        int k0 = 2 * kp, k1 = 2 * kp + 1;
        float v0 = (c < VOC) ? fcn_w[(size_t)k0 * VOC + c]
                             : Ww[(size_t)k0 * ATT + (c - VOC)];
        float v1 = (c < VOC) ? fcn_w[(size_t)k1 * VOC + c]
                             : Ww[(size_t)k1 * ATT + (c - VOC)];
        W2P[i] = h2u(__floats2half2_rn(v0, v1));
    }
}

// features fp32 -> fp16
__global__ void feat2h_kernel(const float* __restrict__ src,
                              __half* __restrict__ dst, int n4) {
    int i = blockIdx.x * blockDim.x + threadIdx.x;
    if (i < n4) {
        float4 v = reinterpret_cast<const float4*>(src)[i];
        uint2 o;
        o.x = h2u(__floats2half2_rn(v.x, v.y));
        o.y = h2u(__floats2half2_rn(v.z, v.w));
        reinterpret_cast<uint2*>(dst)[i] = o;
    }
}

// meanf from fp16 features -> fp16 meanf
__global__ void meanf_h_kernel(const __half* __restrict__ featH,
                               __half* __restrict__ meanfH) {
    int idx = blockIdx.x * blockDim.x + threadIdx.x;
    if (idx >= B * (ENC / 4)) return;
    int b = idx / (ENC / 4);
    int e4 = (idx - b * (ENC / 4)) * 4;
    const __half* p = featH + (size_t)b * NF * ENC + e4;
    float s0 = 0.f, s1 = 0.f, s2 = 0.f, s3 = 0.f;
    #pragma unroll 4
    for (int f = 0; f < NF; ++f) {
        uint2 v = *reinterpret_cast<const uint2*>(p + (size_t)f * ENC);
        float2 lo = __half22float2(*reinterpret_cast<__half2*>(&v.x));
        float2 hi = __half22float2(*reinterpret_cast<__half2*>(&v.y));
        s0 += lo.x; s1 += lo.y; s2 += hi.x; s3 += hi.y;
    }
    const float inv = 1.0f / (float)NF;
    uint2 o;
    o.x = h2u(__floats2half2_rn(s0 * inv, s1 * inv));
    o.y = h2u(__floats2half2_rn(s2 * inv, s3 * inv));
    *reinterpret_cast<uint2*>(meanfH + (size_t)b * ENC + e4) = o;
}

// ---------------- fp16 tensor-core GEMM: C(M,N) = A(M,K) @ B(K,N) ----------
// A: row-major fp16 (lda in halves). Bp: k-pair-packed u32 [K/2][ldb].
// block 64x128, 8 warps (2M x 4N), warp 32x32, mma.m16n8k16.f16.
// MODE 0: atomicAdd fp32 C (K-split via gridDim.z)
// MODE 1: C = acc + bias (fp32)
// MODE 3: Ch = half(acc + bias) (fp16 out)
// Req: m0+64 <= M, K % (32*gridDim.z) == 0, A rows 16B-aligned.
template <int MODE>
__global__ void __launch_bounds__(256)
h16_gemm(const __half* __restrict__ A, int lda,
         const uint32_t* __restrict__ Bp, int ldb,
         float* __restrict__ C, int ldc,
         const float* __restrict__ bias,
         __half* __restrict__ Ch, int ldch,
         int M, int N, int K) {
    __shared__ __align__(16) uint32_t Af[1024];          // 4 KB frag-ready A
    __shared__ __align__(16) uint32_t Bs[2][16][136];    // 17.4 KB

    const int tid  = threadIdx.x;
    const int lane = tid & 31;
    const int warp = tid >> 5;
    const int wm = warp >> 2;
    const int wn = warp & 3;
    const int g = lane >> 2;
    const int t = lane & 3;

    const int m0 = blockIdx.y * 64;
    const int n0 = blockIdx.x * 128;
    const int chunks = (K / 32) / gridDim.z;
    const int kc0 = blockIdx.z * chunks;

    // A staging: thread -> (row r, 8-half segment cseg)
    const int r = tid >> 2;
    const int cseg = tid & 3;
    const int amt = r >> 4;
    const int aks = cseg >> 1;
    const int ae = ((r >> 3) & 1) + ((cseg & 1) << 1);
    const int ag = r & 7;
    const int abase = ((((amt * 2 + aks) << 5) + (ag << 2)) << 2) + ae;

    float acc[2][4][4];
    #pragma unroll
    for (int mi = 0; mi < 2; ++mi)
        #pragma unroll
        for (int ni = 0; ni < 4; ++ni)
            #pragma unroll
            for (int q = 0; q < 4; ++q) acc[mi][ni][q] = 0.f;

    uint4 areg;

    // ---- prologue ----
    {
        const int k0 = kc0 * 32;
        areg = *reinterpret_cast<const uint4*>(A + (size_t)(m0 + r) * lda + k0 + cseg * 8);
        const int kp0 = kc0 * 16;
        #pragma unroll
        for (int i = 0; i < 2; ++i) {
            int j = tid + i * 256;
            int br = j >> 5;
            int bc = (j & 31) * 4;
            int col = n0 + bc;
            const uint32_t* src = Bp + (size_t)(kp0 + br) * ldb + (col < N ? col : 0);
            uint32_t saddr = (uint32_t)__cvta_generic_to_shared(&Bs[0][br][bc]);
            int sz = (col < N) ? 16 : 0;
            asm volatile("cp.async.cg.shared.global [%0], [%1], 16, %2;\n"
                         :: "r"(saddr), "l"(src), "r"(sz));
        }
        asm volatile("cp.async.commit_group;\n");
        Af[abase + 0]  = areg.x;
        Af[abase + 4]  = areg.y;
        Af[abase + 8]  = areg.z;
        Af[abase + 12] = areg.w;
    }

    for (int cc = 0; cc < chunks; ++cc) {
        const int st = cc & 1;
        if (cc + 1 < chunks) {
            const int k0 = (kc0 + cc + 1) * 32;
            const int kp0 = (kc0 + cc + 1) * 16;
            #pragma unroll
            for (int i = 0; i < 2; ++i) {
                int j = tid + i * 256;
                int br = j >> 5;
                int bc = (j & 31) * 4;
                int col = n0 + bc;
                const uint32_t* src = Bp + (size_t)(kp0 + br) * ldb + (col < N ? col : 0);
                uint32_t saddr = (uint32_t)__cvta_generic_to_shared(&Bs[st ^ 1][br][bc]);
                int sz = (col < N) ? 16 : 0;
                asm volatile("cp.async.cg.shared.global [%0], [%1], 16, %2;\n"
                             :: "r"(saddr), "l"(src), "r"(sz));
            }
            areg = *reinterpret_cast<const uint4*>(A + (size_t)(m0 + r) * lda + k0 + cseg * 8);
        }
        asm volatile("cp.async.commit_group;\n");
        asm volatile("cp.async.wait_group 1;\n");
        __syncthreads();

        #pragma unroll
        for (int ks = 0; ks < 2; ++ks) {
            uint32_t af[2][4];
            #pragma unroll
            for (int mi = 0; mi < 2; ++mi) {
                int mt = wm * 2 + mi;
                uint4 a = *reinterpret_cast<const uint4*>(
                    &Af[(((mt * 2 + ks) << 5) + lane) << 2]);
                af[mi][0] = a.x; af[mi][1] = a.y; af[mi][2] = a.z; af[mi][3] = a.w;
            }
            #pragma unroll
            for (int ni = 0; ni < 4; ++ni) {
                int cB = wn * 32 + ni * 8 + g;
                uint32_t b0 = Bs[st][ks * 8 + t][cB];
                uint32_t b1 = Bs[st][ks * 8 + t + 4][cB];
                #pragma unroll
                for (int mi = 0; mi < 2; ++mi) {
                    asm volatile(
                        "mma.sync.aligned.m16n8k16.row.col.f32.f16.f16.f32 "
                        "{%0,%1,%2,%3}, {%4,%5,%6,%7}, {%8,%9}, {%0,%1,%2,%3};"
                        : "+f"(acc[mi][ni][0]), "+f"(acc[mi][ni][1]),
                          "+f"(acc[mi][ni][2]), "+f"(acc[mi][ni][3])
                        : "r"(af[mi][0]), "r"(af[mi][1]),
                          "r"(af[mi][2]), "r"(af[mi][3]),
                          "r"(b0), "r"(b1));
                }
            }
        }
        __syncthreads();
        if (cc + 1 < chunks) {
            Af[abase + 0]  = areg.x;
            Af[abase + 4]  = areg.y;
            Af[abase + 8]  = areg.z;
            Af[abase + 12] = areg.w;
        }
    }

    // epilogue: c0:(g,2t) c1:(g,2t+1) c2:(g+8,2t) c3:(g+8,2t+1)
    #pragma unroll
    for (int mi = 0; mi < 2; ++mi) {
        int r0 = m0 + wm * 32 + mi * 16 + g;
        #pragma unroll
        for (int ni = 0; ni < 4; ++ni) {
            int col = n0 + wn * 32 + ni * 8 + 2 * t;
            if (col >= N) continue;
            if (MODE == 0) {
                atomicAdd(&C[(size_t)r0 * ldc + col],           acc[mi][ni][0]);
                atomicAdd(&C[(size_t)r0 * ldc + col + 1],       acc[mi][ni][1]);
                atomicAdd(&C[(size_t)(r0 + 8) * ldc + col],     acc[mi][ni][2]);
                atomicAdd(&C[(size_t)(r0 + 8) * ldc + col + 1], acc[mi][ni][3]);
            } else if (MODE == 1) {
                float bv0 = bias[col], bv1 = bias[col + 1];
                float2 v0 = make_float2(acc[mi][ni][0] + bv0, acc[mi][ni][1] + bv1);
                float2 v1 = make_float2(acc[mi][ni][2] + bv0, acc[mi][ni][3] + bv1);
                *reinterpret_cast<float2*>(&C[(size_t)r0 * ldc + col]) = v0;
                *reinterpret_cast<float2*>(&C[(size_t)(r0 + 8) * ldc + col]) = v1;
            } else {
                float bv0 = bias[col], bv1 = bias[col + 1];
                __half2 v0 = __floats2half2_rn(acc[mi][ni][0] + bv0, acc[mi][ni][1] + bv1);
                __half2 v1 = __floats2half2_rn(acc[mi][ni][2] + bv0, acc[mi][ni][3] + bv1);
                *reinterpret_cast<__half2*>(&Ch[(size_t)r0 * ldch + col]) = v0;
                *reinterpret_cast<__half2*>(&Ch[(size_t)(r0 + 8) * ldch + col]) = v1;
            }
        }
    }
}

// ---------------- scores: grid (4, B), 256 threads ----------------
__global__ void __launch_bounds__(256)
scores_kernel(const __half* __restrict__ uhsH,
              const float* __restrict__ wah,
              const float* __restrict__ Aw,
              const float* __restrict__ Ab,
              const int* __restrict__ captions,
              const float* __restrict__ emb,
              const float* __restrict__ bcat,
              const __half* __restrict__ hrH,
              __half* __restrict__ incatH,
              float* __restrict__ gates,
              float* __restrict__ scores,
              int t) {
    const int q = blockIdx.x;
    const int b = blockIdx.y;
    const int tid = threadIdx.x;
    const int warp = tid >> 5;
    const int lane = tid & 31;

    __shared__ __align__(16) float s_wah[ATT];
    __shared__ __align__(16) float s_Aw[ATT];

    for (int i = tid; i < ATT; i += 256) {
        s_wah[i] = wah[b * ATT + i];
        s_Aw[i]  = Aw[i];
    }
    __syncthreads();

    // glue, slice q
    {
        int tok = captions[b * (TSTEPS + 1) + t];
        if (tid < 128) {
            int iq = q * 128 + tid;
            incatH[(size_t)b * KCAT + iq] = __float2half_rn(emb[(size_t)tok * EMB + iq]);
            incatH[(size_t)b * KCAT + EMB + ENC + iq] = hrH[b * DEC + iq];
        }
        int i0 = q * 512 + tid;
        gates[(size_t)b * GATES4 + i0]       = bcat[i0];
        gates[(size_t)b * GATES4 + i0 + 256] = bcat[i0 + 256];
    }

    const float Ab0 = Ab[0];
    const int f0 = q * 49;
    for (int f = f0 + warp; f < f0 + 49; f += 8) {
        const __half* u = uhsH + ((size_t)(b * NF + f)) * ATT;
        float a0 = 0.f, a1 = 0.f, a2 = 0.f, a3 = 0.f;
        #pragma unroll
        for (int kk = 0; kk < 4; ++kk) {
            int k = kk * 128 + lane * 4;
            uint2 uv = *reinterpret_cast<const uint2*>(u + k);
            float2 f01 = __half22float2(*reinterpret_cast<__half2*>(&uv.x));
            float2 f23 = __half22float2(*reinterpret_cast<__half2*>(&uv.y));
            float4 wv = *reinterpret_cast<const float4*>(&s_wah[k]);
            float4 av = *reinterpret_cast<const float4*>(&s_Aw[k]);
            a0 += htanh(f01.x + wv.x) * av.x;
            a1 += htanh(f01.y + wv.y) * av.y;
            a2 += htanh(f23.x + wv.z) * av.z;
            a3 += htanh(f23.y + wv.w) * av.w;
        }
        float acc = (a0 + a1) + (a2 + a3);
        #pragma unroll
        for (int o = 16; o; o >>= 1) acc += __shfl_xor_sync(0xffffffffu, acc, o);
        if (lane == 0) scores[b * NF + f] = acc + Ab0;
    }
}

// ---------------- ctx: softmax + context slice, grid (4, B), 512 threads ----
__global__ void __launch_bounds__(512)
ctx_kernel(const float* __restrict__ scores,
           const __half* __restrict__ featH,
           __half* __restrict__ incatH,
           float* __restrict__ alpha_out) {
    const int y = blockIdx.x;
    const int b = blockIdx.y;
    const int tid = threadIdx.x;
    const int warp = tid >> 5;
    const int lane = tid & 31;

    __shared__ float s_al[NF];
    __shared__ float s_red[16];
    __shared__ __align__(16) float4 s_part[4][128];

    float v = (tid < NF) ? scores[b * NF + tid] : -1e30f;
    float m = v;
    #pragma unroll
    for (int o = 16; o; o >>= 1) m = fmaxf(m, __shfl_xor_sync(0xffffffffu, m, o));
    if (lane == 0) s_red[warp] = m;
    __syncthreads();
    if (tid == 0) {
        float mm = s_red[0];
        #pragma unroll
        for (int w = 1; w < 16; ++w) mm = fmaxf(mm, s_red[w]);
        s_red[0] = mm;
    }
    __syncthreads();
    const float mx = s_red[0];
    __syncthreads();
    float e = (tid < NF) ? expf(v - mx) : 0.f;
    float s = e;
    #pragma unroll
    for (int o = 16; o; o >>= 1) s += __shfl_xor_sync(0xffffffffu, s, o);
    if (lane == 0) s_red[warp] = s;
    __syncthreads();
    if (tid == 0) {
        float ss = 0.f;
        #pragma unroll
        for (int w = 0; w < 16; ++w) ss += s_red[w];
        s_red[0] = ss;
    }
    __syncthreads();
    const float inv_denom = 1.0f / s_red[0];
    if (tid < NF) {
        float alpha = e * inv_denom;
        s_al[tid] = alpha;
        if (y == 0)
            alpha_out[(size_t)b * (TSTEPS * NF) + tid] = alpha;
    }
    __syncthreads();

    const int sub = tid >> 7;
    const int c4  = tid & 127;
    const int col = y * 512 + c4 * 4;
    const __half* fp = featH + (size_t)b * NF * ENC + col;
    float cx = 0.f, cy = 0.f, cz = 0.f, cw = 0.f;
    const int fs = sub * 49;
    #pragma unroll 7
    for (int f = fs; f < fs + 49; ++f) {
        uint2 fv = *reinterpret_cast<const uint2*>(fp + (size_t)f * ENC);
        float2 lo = __half22float2(*reinterpret_cast<__half2*>(&fv.x));
        float2 hi = __half22float2(*reinterpret_cast<__half2*>(&fv.y));
        float a = s_al[f];
        cx += a * lo.x; cy += a * lo.y; cz += a * hi.x; cw += a * hi.y;
    }
    s_part[sub][c4] = make_float4(cx, cy, cz, cw);
    __syncthreads();
    if (tid < 128) {
        float4 p0 = s_part[0][tid], p1 = s_part[1][tid];
        float4 p2 = s_part[2][tid], p3 = s_part[3][tid];
        uint2 o;
        o.x = h2u(__floats2half2_rn(p0.x + p1.x + p2.x + p3.x,
                                    p0.y + p1.y + p2.y + p3.y));
        o.y = h2u(__floats2half2_rn(p0.z + p1.z + p2.z + p3.z,
                                    p0.w + p1.w + p2.w + p3.w));
        *reinterpret_cast<uint2*>(
            &incatH[(size_t)b * KCAT + EMB + y * 512 + tid * 4]) = o;
    }
}

// ---------------- LSTM pointwise + wah bias-init ----------------
__global__ void lstm_kernel(const float* __restrict__ gates,
                            __half* __restrict__ hrH,
                            float* __restrict__ c,
                            float* __restrict__ wah,
                            const float* __restrict__ Wb) {
    int idx = blockIdx.x * blockDim.x + threadIdx.x;
    if (idx >= B * DEC) return;
    int b = idx / DEC;
    int n = idx - b * DEC;
    const float* g = gates + (size_t)b * GATES4;
    float i_ = g[n];
    float f_ = g[DEC + n];
    float gg = g[2 * DEC + n];
    float o_ = g[3 * DEC + n];
    float cc = c[idx];
    cc = sigmoidf_(f_) * cc + sigmoidf_(i_) * tanhf(gg);
    c[idx] = cc;
    hrH[idx] = __float2half_rn(sigmoidf_(o_) * tanhf(cc));
    wah[idx] = Wb[idx & (ATT - 1)];
}

// ---------------- launch ----------------
extern "C" void kernel_launch(void* const* d_in, const int* in_sizes, int n_in,
                              void* d_out, int out_size) {
    const float* features = (const float*)d_in[0];
    const int*   captions = (const int*)  d_in[1];
    const float* emb      = (const float*)d_in[2];
    const float* Uw       = (const float*)d_in[3];
    const float* Ub       = (const float*)d_in[4];
    const float* Ww       = (const float*)d_in[5];
    const float* Wb       = (const float*)d_in[6];
    const float* Aw       = (const float*)d_in[7];
    const float* Ab       = (const float*)d_in[8];
    const float* ih_w     = (const float*)d_in[9];
    const float* ih_b     = (const float*)d_in[10];
    const float* ic_w     = (const float*)d_in[11];
    const float* ic_b     = (const float*)d_in[12];
    const float* W_ih     = (const float*)d_in[13];
    const float* b_ih     = (const float*)d_in[14];
    const float* W_hh     = (const float*)d_in[15];
    const float* b_hh     = (const float*)d_in[16];
    const float* fcn_w    = (const float*)d_in[17];
    const float* fcn_b    = (const float*)d_in[18];
    float* out = (float*)d_out;

    float* S = nullptr;
    cudaGetSymbolAddress((void**)&S, g_scratch);
    __half*   uhsH   = reinterpret_cast<__half*>(S + OFF_UHSH);
    uint32_t* WcatP  = reinterpret_cast<uint32_t*>(S + OFF_WCATP);
    uint32_t* W2P    = reinterpret_cast<uint32_t*>(S + OFF_W2P);
    uint32_t* ihP    = reinterpret_cast<uint32_t*>(S + OFF_IHP);
    uint32_t* icP    = reinterpret_cast<uint32_t*>(S + OFF_ICP);
    uint32_t* UwP    = reinterpret_cast<uint32_t*>(S + OFF_UWP);
    __half*   featH  = reinterpret_cast<__half*>(S + OFF_FEATH);
    __half*   meanfH = reinterpret_cast<__half*>(S + OFF_MEANFH);
    float*    c      = S + OFF_C;
    __half*   hrH[2] = { reinterpret_cast<__half*>(S + OFF_HRH0),
                         reinterpret_cast<__half*>(S + OFF_HRH1) };
    float*    wah    = S + OFF_WAH;
    __half*   incatH = reinterpret_cast<__half*>(S + OFF_INCATH);
    float*    gates  = S + OFF_GATES;
    float*    bcat   = S + OFF_BCAT;
    float*    sc     = S + OFF_SC;

    cudaStream_t s2;
    cudaStreamCreateWithFlags(&s2, cudaStreamNonBlocking);
    cudaEvent_t fork_ev[2], join_ev[2], prep_ev, pjoin_ev;
    for (int i = 0; i < 2; ++i) {
        cudaEventCreateWithFlags(&fork_ev[i], cudaEventDisableTiming);
        cudaEventCreateWithFlags(&join_ev[i], cudaEventDisableTiming);
    }
    cudaEventCreateWithFlags(&prep_ev, cudaEventDisableTiming);
    cudaEventCreateWithFlags(&pjoin_ev, cudaEventDisableTiming);

    // ---- prep ----
    prep_wcat_kernel<<<2048, 256>>>(W_ih, W_hh, b_ih, b_hh, WcatP, bcat);
    prep_w2_kernel<<<2048, 256>>>(fcn_w, Ww, W2P);
    feat2h_kernel<<<(B * NF * ENC / 4 + 255) / 256, 256>>>(
        features, featH, B * NF * ENC / 4);
    pack_weight_kernel<<<512, 256>>>(Uw, UwP, ENC, ATT);
    pack_weight_kernel<<<512, 256>>>(ih_w, ihP, ENC, DEC);
    pack_weight_kernel<<<512, 256>>>(ic_w, icP, ENC, DEC);
    cudaEventRecord(prep_ev, 0);

    // side chain on s2: meanf -> h0 -> c0 -> wah0 (overlaps uhs GEMM)
    cudaStreamWaitEvent(s2, prep_ev, 0);
    meanf_h_kernel<<<(B * (ENC / 4) + 255) / 256, 256, 0, s2>>>(featH, meanfH);
    h16_gemm<3><<<dim3(DEC / 128, 1, 1), 256, 0, s2>>>(meanfH, ENC, ihP, DEC,
        nullptr, 0, ih_b, hrH[1], DEC, B, DEC, ENC);
    h16_gemm<1><<<dim3(DEC / 128, 1, 1), 256, 0, s2>>>(meanfH, ENC, icP, DEC,
        c, DEC, ic_b, nullptr, 0, B, DEC, ENC);
    h16_gemm<1><<<dim3(ATT / 128, 1, 1), 256, 0, s2>>>(hrH[1], DEC, W2P + VOC, N2,
        wah, ATT, Wb, nullptr, 0, B, ATT, DEC);
    cudaEventRecord(pjoin_ev, s2);

    // main: u_hs = featH @ UwP + Ub -> fp16 uhsH  (12544 x 512 x 2048)
    h16_gemm<3><<<dim3(ATT / 128, (B * NF) / 64, 1), 256>>>(featH, ENC, UwP, ATT,
        nullptr, 0, Ub, uhsH, ATT, B * NF, ATT, ENC);
    cudaStreamWaitEvent(0, pjoin_ev, 0);

    // ---- recurrent steps ----
    for (int t = 0; t < TSTEPS; ++t) {
        float* alpha_t = out + ALPHA_OFF + (size_t)t * NF;
        __half* hr_in  = hrH[(t + 1) & 1];
        __half* hr_out = hrH[t & 1];

        scores_kernel<<<dim3(4, B), 256>>>(uhsH, wah, Aw, Ab, captions, emb,
                                           bcat, hr_in, incatH, gates, sc, t);
        ctx_kernel<<<dim3(4, B), 512>>>(sc, featH, incatH, alpha_t);
        h16_gemm<0><<<dim3(GATES4 / 128, 1, 8), 256>>>(incatH, KCAT, WcatP, GATES4,
            gates, GATES4, nullptr, nullptr, 0, B, GATES4, KCAT);
        if (t >= 2) cudaStreamWaitEvent(0, join_ev[t & 1], 0);
        lstm_kernel<<<(B * DEC + 255) / 256, 256>>>(gates, hr_out, c, wah, Wb);
        cudaEventRecord(fork_ev[t & 1], 0);
        // wah_{t+1} = h_{t+1} @ Ww + Wb (critical path)
        h16_gemm<0><<<dim3(ATT / 128, 1, 4), 256>>>(hr_out, DEC, W2P + VOC, N2,
            wah, ATT, nullptr, nullptr, 0, B, ATT, DEC);
        // preds_t — off critical path on s2
        cudaStreamWaitEvent(s2, fork_ev[t & 1], 0);
        h16_gemm<1><<<dim3((VOC + 127) / 128, 1, 1), 256, 0, s2>>>(hr_out, DEC,
            W2P, N2, out + (size_t)t * VOC, TSTEPS * VOC, fcn_b, nullptr, 0,
            B, VOC, DEC);
        cudaEventRecord(join_ev[t & 1], s2);
    }
    cudaStreamWaitEvent(0, join_ev[(TSTEPS - 1) & 1], 0);
    cudaStreamWaitEvent(0, join_ev[(TSTEPS - 2) & 1], 0);
}